// round 10
// baseline (speedup 1.0000x reference)
#include <cuda_runtime.h>
#include <math.h>
#include <stdint.h>

// Problem constants
#define PB 32
#define PN 2048
#define PH 128
#define PG4 512
#define PM (PB * PN)   // 65536 rows
#define PK 256         // combined K = [X | H]

// ---------------- device scratch (no allocations allowed) ----------------
__device__ float g_contrib[(size_t)PM * PG4];   // [c0 | h0 | c1 | h1] per row
__device__ float g_WT0[PG4 * PK];               // B operand, layer0: [n][k], tf32-rounded
__device__ float g_WT1[PG4 * PK];               // layer1
__device__ float g_bP0[PG4];
__device__ float g_bP1[PG4];
__device__ float g_ipnew[PM];
__device__ int   g_cnt[PM];                     // incoming-edge counts per target
__device__ int   g_off[PM];                     // CSR offsets
__device__ int   g_cur[PM];                     // fill cursors (post-fill: off + filled)
__device__ int   g_esrc[3 * PM];                // edge source rows
__device__ float g_ew[3 * PM];                  // edge weights

// ---------------- helpers ----------------
__device__ __forceinline__ uint32_t smem_u32(const void* p) {
    uint32_t a;
    asm("{ .reg .u64 t; cvta.to.shared.u64 t, %1; cvt.u32.u64 %0, t; }" : "=r"(a) : "l"(p));
    return a;
}
__device__ __forceinline__ uint32_t f2tf32(float x) {
    uint32_t r;
    asm("cvt.rna.tf32.f32 %0, %1;" : "=r"(r) : "f"(x));
    return r;
}
__device__ __forceinline__ void mma8(float* d, const uint32_t* a, uint32_t b0, uint32_t b1) {
    asm volatile(
        "mma.sync.aligned.m16n8k8.row.col.f32.tf32.tf32.f32 "
        "{%0,%1,%2,%3}, {%4,%5,%6,%7}, {%8,%9}, {%0,%1,%2,%3};"
        : "+f"(d[0]), "+f"(d[1]), "+f"(d[2]), "+f"(d[3])
        : "r"(a[0]), "r"(a[1]), "r"(a[2]), "r"(a[3]), "r"(b0), "r"(b1));
}
__device__ __forceinline__ void ldsm4(uint32_t& r0, uint32_t& r1, uint32_t& r2, uint32_t& r3,
                                      uint32_t addr) {
    asm volatile("ldmatrix.sync.aligned.m8n8.x4.shared.b16 {%0,%1,%2,%3}, [%4];"
                 : "=r"(r0), "=r"(r1), "=r"(r2), "=r"(r3) : "r"(addr));
}
#define CP_ASYNC16(s, g) asm volatile("cp.async.cg.shared.global [%0], [%1], 16;" :: "r"(s), "l"(g))
#define CP_COMMIT() asm volatile("cp.async.commit_group;" ::: "memory")
#define CP_WAIT0() asm volatile("cp.async.wait_group 0;" ::: "memory")
#define CP_WAIT1() asm volatile("cp.async.wait_group 1;" ::: "memory")

__device__ __forceinline__ float sigf(float x) {
    return __fdividef(1.0f, 1.0f + __expf(-x));
}
__device__ __forceinline__ float tanhf_f(float x) {
    float xc = fminf(fmaxf(x, -15.0f), 15.0f);
    float e = __expf(2.0f * xc);
    return __fdividef(e - 1.0f, e + 1.0f);
}

// ---------------- weight prep (bias merged in) ----------------
// Gate-column permutation: for unit u (0..127), gate g (i=0,f=1,g=2,o=3):
//   c(u,g) = (u>>2)*16 + (u&3)*2 + (g&1) + (g>>1)*8
__device__ __forceinline__ int perm_oc(int n) {
    int blk = n >> 4, w = n & 15;
    int ghi = w >> 3, pos = (w & 7) >> 1, glo = w & 1;
    int u = blk * 4 + pos;
    int g = ghi * 2 + glo;
    return g * 128 + u;
}
__global__ void ip_permW(const float* __restrict__ Wi, const float* __restrict__ Wh,
                         const float* __restrict__ bsrc,
                         float* __restrict__ WT, float* __restrict__ bdst)
{
    int t = blockIdx.x * 256 + threadIdx.x;    // [0, 512*256)
    int n = t >> 8;
    int k = t & 255;
    int oc = perm_oc(n);
    float w = (k < 128) ? Wi[k * PG4 + oc] : Wh[(k - 128) * PG4 + oc];
    WT[t] = __uint_as_float(f2tf32(w));
    if (k == 0) bdst[n] = bsrc[oc];
}

// ---------------- CSR helpers ----------------
__global__ void ip_zcnt()
{
    int i = blockIdx.x * 256 + threadIdx.x;    // grid 64 x 256 covers 16384 x4
    ((int4*)g_cnt)[i] = make_int4(0, 0, 0, 0);
}
__global__ void ip_count(const int* __restrict__ ti, const int* __restrict__ fi,
                         const int* __restrict__ ri)
{
    int s = blockIdx.x * 256 + threadIdx.x;
    int bb = (s >> 11) << 11;
    atomicAdd(&g_cnt[bb + ri[s]], 1);
    atomicAdd(&g_cnt[bb + ti[s]], 1);
    atomicAdd(&g_cnt[bb + fi[s]], 1);
}
__global__ void ip_pad() {}

// ---------------- CSR: per-batch exclusive scan of counts; zero ipnew ------
__global__ __launch_bounds__(512) void ip_scan()
{
    __shared__ int part[512];
    int b = blockIdx.x;          // 32 batches
    int t = threadIdx.x;         // 512
    int base = b << 11;

    int c0 = g_cnt[base + 4 * t + 0];
    int c1 = g_cnt[base + 4 * t + 1];
    int c2 = g_cnt[base + 4 * t + 2];
    int c3 = g_cnt[base + 4 * t + 3];
    int l0 = c0, l1 = l0 + c1, l2 = l1 + c2, l3 = l2 + c3;
    part[t] = l3;
    __syncthreads();
    for (int o = 1; o < 512; o <<= 1) {
        int v = (t >= o) ? part[t - o] : 0;
        __syncthreads();
        part[t] += v;
        __syncthreads();
    }
    int ex = (t == 0) ? 0 : part[t - 1];
    int gb = b * 6144 + ex;
    g_off[base + 4 * t + 0] = gb;
    g_off[base + 4 * t + 1] = gb + l0;
    g_off[base + 4 * t + 2] = gb + l1;
    g_off[base + 4 * t + 3] = gb + l2;
    g_cur[base + 4 * t + 0] = gb;
    g_cur[base + 4 * t + 1] = gb + l0;
    g_cur[base + 4 * t + 2] = gb + l1;
    g_cur[base + 4 * t + 3] = gb + l2;
    g_ipnew[base + 4 * t + 0] = 0.0f;
    g_ipnew[base + 4 * t + 1] = 0.0f;
    g_ipnew[base + 4 * t + 2] = 0.0f;
    g_ipnew[base + 4 * t + 3] = 0.0f;
}

// ---------------- tf32 mma.sync GEMM + fused LSTM epilogue ----------------
// CTA: 128 rows x 128 gate-cols. 8 warps (4 M x 2 N), warp tile 32x64.
// K = 256 in 8 chunks of 32. 3-stage all-cp.async pipeline; frags via ldmatrix.
#define A_STRIDE 36
#define HALF_STAGE (128 * A_STRIDE * 4)          // 18432 (A part)
#define STAGE_BYTES (2 * HALF_STAGE)             // 36864 (A + B)
#define SMEM_TOTAL_GEMM (3 * STAGE_BYTES)        // 110592

__global__ __launch_bounds__(256, 2) void ip_lstm_mma(
    const float* __restrict__ X, int xs,
    const float* __restrict__ Hp, int hs,
    const float* __restrict__ Cold,
    const float* __restrict__ WT, const float* __restrict__ bP,
    float* __restrict__ outC, float* __restrict__ outH)
{
    extern __shared__ char smem[];

    int tid = threadIdx.x;
    int wid = tid >> 5, lane = tid & 31;
    int wm = wid & 3, wn = wid >> 2;          // 4 M-warps x 2 N-warps
    int row0 = blockIdx.y * 128;
    int col0 = blockIdx.x * 128;

    float acc[2][8][4];
#pragma unroll
    for (int mt = 0; mt < 2; mt++)
#pragma unroll
        for (int nt = 0; nt < 8; nt++)
#pragma unroll
            for (int q = 0; q < 4; q++) acc[mt][nt][q] = 0.0f;

    float bI[4], bF[4], bG[4], bO[4];
#pragma unroll
    for (int p = 0; p < 4; p++) {
        int c0 = col0 + wn * 64 + p * 16 + (lane & 3) * 2;
        bI[p] = bP[c0];     bF[p] = bP[c0 + 1];
        bG[p] = bP[c0 + 8]; bO[p] = bP[c0 + 9];
    }

    // ldmatrix per-thread address bases (stage 0; add stage offset + ks*32 per use)
    // tile t = lane>>3: t0 rows0-7/k+0, t1 rows8-15/k+0, t2 rows0-7/k+4, t3 rows8-15/k+4
    uint32_t sb = smem_u32(smem);
    int lt = lane >> 3;
    int lrow = ((lt & 1) << 3) + (lane & 7);
    int lcol = (lt >> 1) << 2;
    uint32_t aAddr[2], bAddr[4];
#pragma unroll
    for (int mt = 0; mt < 2; mt++)
        aAddr[mt] = sb + ((wm * 32 + mt * 16 + lrow) * A_STRIDE + lcol) * 4;
#pragma unroll
    for (int P = 0; P < 4; P++)
        bAddr[P] = sb + HALF_STAGE + ((wn * 64 + P * 16 + lrow) * A_STRIDE + lcol) * 4;

    auto prefetch = [&](int c) {
        const float* Asrc = (c < 4) ? X : Hp;
        int astr = (c < 4) ? xs : hs;
        int ka = (c & 3) * 32;
        int kb = c * 32;
        char* As = smem + (c % 3) * STAGE_BYTES;
        char* Bs = As + HALF_STAGE;
#pragma unroll
        for (int j = 0; j < 4; j++) {
            int fid = j * 256 + tid;
            int r = fid >> 3, q = fid & 7;
            CP_ASYNC16(smem_u32(As + r * (A_STRIDE * 4) + q * 16),
                       Asrc + (size_t)(row0 + r) * astr + ka + q * 4);
            CP_ASYNC16(smem_u32(Bs + r * (A_STRIDE * 4) + q * 16),
                       WT + (size_t)(col0 + r) * PK + kb + q * 4);
        }
    };

    // prologue: stages 0 and 1 in flight
    prefetch(0); CP_COMMIT();
    prefetch(1); CP_COMMIT();
    CP_WAIT1();
    __syncthreads();

#pragma unroll 1
    for (int ch = 0; ch < 8; ch++) {
        // issue next prefetch FIRST so cp.async overlaps the whole mma chain
        if (ch < 6) { prefetch(ch + 2); CP_COMMIT(); }

        uint32_t stg = (uint32_t)((ch % 3) * STAGE_BYTES);
#pragma unroll
        for (int ks = 0; ks < 4; ks++) {
            uint32_t ko = stg + ks * 32;
            uint32_t a[2][4];
#pragma unroll
            for (int mt = 0; mt < 2; mt++)
                ldsm4(a[mt][0], a[mt][1], a[mt][2], a[mt][3], aAddr[mt] + ko);
            uint32_t bq[4][4];
#pragma unroll
            for (int P = 0; P < 4; P++)
                ldsm4(bq[P][0], bq[P][1], bq[P][2], bq[P][3], bAddr[P] + ko);
#pragma unroll
            for (int mt = 0; mt < 2; mt++)
#pragma unroll
                for (int nt = 0; nt < 8; nt++) {
                    int P = nt >> 1, j = nt & 1;
                    mma8(acc[mt][nt], a[mt], bq[P][j], bq[P][j + 2]);
                }
        }

        if (ch < 7) {
            if (ch < 6) CP_WAIT1(); else CP_WAIT0();
            __syncthreads();
        }
    }

    // ---- fused LSTM epilogue ----
#pragma unroll
    for (int mt = 0; mt < 2; mt++) {
        int r = row0 + wm * 32 + mt * 16 + (lane >> 2);
#pragma unroll
        for (int p = 0; p < 4; p++) {
            int u = (col0 >> 2) + wn * 16 + p * 4 + (lane & 3);
            float co0 = Cold[(size_t)r * PH + u];
            float co1 = Cold[(size_t)(r + 8) * PH + u];
            float iv = acc[mt][2 * p][0] + bI[p];
            float fv = acc[mt][2 * p][1] + bF[p];
            float gv = acc[mt][2 * p + 1][0] + bG[p];
            float ov = acc[mt][2 * p + 1][1] + bO[p];
            float cn0 = sigf(fv) * co0 + sigf(iv) * tanhf_f(gv);
            float hn0 = sigf(ov) * tanhf_f(cn0);
            float iv1 = acc[mt][2 * p][2] + bI[p];
            float fv1 = acc[mt][2 * p][3] + bF[p];
            float gv1 = acc[mt][2 * p + 1][2] + bG[p];
            float ov1 = acc[mt][2 * p + 1][3] + bO[p];
            float cn1 = sigf(fv1) * co1 + sigf(iv1) * tanhf_f(gv1);
            float hn1 = sigf(ov1) * tanhf_f(cn1);

            outC[(size_t)r * PG4 + u] = cn0;
            outH[(size_t)r * PG4 + u] = hn0;
            outC[(size_t)(r + 8) * PG4 + u] = cn1;
            outH[(size_t)(r + 8) * PG4 + u] = hn1;
        }
    }
}

// ---------------- mask exit/raise nodes: contrib <- old state ----------------
__global__ void ip_mask(const float* __restrict__ hc0, const float* __restrict__ hh0,
                        const float* __restrict__ hc1, const float* __restrict__ hh1,
                        const int* __restrict__ exi, const int* __restrict__ rai)
{
    int b = blockIdx.x;
    int node = blockIdx.y ? rai[b] : exi[b];
    int tid = threadIdx.x;  // 128
    size_t r = (size_t)b * PN + node;
    float* dst = g_contrib + r * PG4;
    size_t rb = r * PH;
    dst[tid]       = hc0[rb + tid];
    dst[128 + tid] = hh0[rb + tid];
    dst[256 + tid] = hc1[rb + tid];
    dst[384 + tid] = hh1[rb + tid];
}

// ---------------- decision heads + CSR edge fill + ip scatter ----------------
__global__ __launch_bounds__(256) void ip_decision(
    const float* __restrict__ Wr, const float* __restrict__ brs,
    const float* __restrict__ Wb, const float* __restrict__ bbs,
    const float* __restrict__ ipin,
    const int* __restrict__ ti, const int* __restrict__ fi, const int* __restrict__ ri,
    const int* __restrict__ exi, const int* __restrict__ rai,
    const int* __restrict__ slim, const int* __restrict__ cstep, int cs_fallback)
{
    __shared__ float sW[2048];  // [0:1024) W_raise, [1024:2048) W_branch
    int tid = threadIdx.x;
    for (int i = tid; i < 1024; i += 256) { sW[i] = Wr[i]; sW[1024 + i] = Wb[i]; }
    __syncthreads();

    int lane = tid & 31;
    int row = blockIdx.x * 8 + (tid >> 5);
    int b = row >> 11, n = row & 2047;

    int cs = cstep ? cstep[0] : cs_fallback;
    if (cs >= slim[b]) return;

    const float* crow = g_contrib + (size_t)row * PG4;
    float4 v[4];
#pragma unroll
    for (int t2 = 0; t2 < 4; t2++) v[t2] = *(const float4*)&crow[lane * 4 + t2 * 128];

    float r0 = 0.f, r1 = 0.f, q0 = 0.f, q1 = 0.f;
#pragma unroll
    for (int t2 = 0; t2 < 4; t2++) {
        int cb = lane * 4 + t2 * 128;
        float vv[4] = {v[t2].x, v[t2].y, v[t2].z, v[t2].w};
#pragma unroll
        for (int q = 0; q < 4; q++) {
            float w = vv[q];
            int c2 = (cb + q) * 2;
            r0 = fmaf(w, sW[c2 + 0], r0);
            r1 = fmaf(w, sW[c2 + 1], r1);
            q0 = fmaf(w, sW[1024 + c2 + 0], q0);
            q1 = fmaf(w, sW[1024 + c2 + 1], q1);
        }
    }
#pragma unroll
    for (int o = 16; o > 0; o >>= 1) {
        r0 += __shfl_xor_sync(0xffffffffu, r0, o);
        r1 += __shfl_xor_sync(0xffffffffu, r1, o);
        q0 += __shfl_xor_sync(0xffffffffu, q0, o);
        q1 += __shfl_xor_sync(0xffffffffu, q1, o);
    }

    float lr = (r0 + brs[0]) - (r1 + brs[1]);
    float p_raise = 1.0f / (1.0f + expf(-lr));
    float p_no = 1.0f - p_raise;
    if (n == exi[b] || n == rai[b]) { p_raise = 0.0f; p_no = 1.0f; }
    float lb = (q0 + bbs[0]) - (q1 + bbs[1]);
    float pb0 = 1.0f / (1.0f + expf(-lb));
    float pb1 = 1.0f - pb0;

    float ipv = ipin[row];
    float wr_ = p_raise * ipv;
    float wt_ = p_no * pb0 * ipv;
    float wf_ = p_no * pb1 * ipv;

    if (lane == 0) {
        int bb2 = b << 11;
        int tr = bb2 + ri[row], tt = bb2 + ti[row], tf = bb2 + fi[row];
        atomicAdd(&g_ipnew[tr], wr_);
        atomicAdd(&g_ipnew[tt], wt_);
        atomicAdd(&g_ipnew[tf], wf_);
        if (wr_ != 0.0f) {
            int s = atomicAdd(&g_cur[tr], 1);
            g_esrc[s] = row; g_ew[s] = wr_;
        }
        if (wt_ != 0.0f) {
            int s = atomicAdd(&g_cur[tt], 1);
            g_esrc[s] = row; g_ew[s] = wt_;
        }
        if (wf_ != 0.0f) {
            int s = atomicAdd(&g_cur[tf], 1);
            g_esrc[s] = row; g_ew[s] = wf_;
        }
    }
}

// ---------------- gather + finalize: one pass, no atomics, no accum ----------
__global__ __launch_bounds__(128) void ip_gather(
    const float* __restrict__ hc0, const float* __restrict__ hh0,
    const float* __restrict__ hc1, const float* __restrict__ hh1,
    const float* __restrict__ ipold, const int* __restrict__ slim,
    const int* __restrict__ cstep, int cs_fallback, float* __restrict__ out)
{
    int row = blockIdx.x;
    int tid = threadIdx.x;  // 128
    int b = row >> 11;
    int cs = cstep ? cstep[0] : cs_fallback;
    bool nd = cs < slim[b];
    size_t ob = (size_t)row * 513;
    if (nd) {
        int s = g_off[row], e = g_cur[row];
        const float4* cb = (const float4*)g_contrib;
        float ax = 0.f, ay = 0.f, az = 0.f, aw = 0.f;
        for (int i = s; i < e; i++) {
            float w = g_ew[i];
            int src = g_esrc[i];
            float4 v = cb[(size_t)src * 128 + tid];
            ax = fmaf(w, v.x, ax); ay = fmaf(w, v.y, ay);
            az = fmaf(w, v.z, az); aw = fmaf(w, v.w, aw);
        }
        float ipn = g_ipnew[row];
        float inv = __fdividef(1.0f, ipn + 1e-7f);
        out[ob + 4 * tid + 0] = ax * inv;
        out[ob + 4 * tid + 1] = ay * inv;
        out[ob + 4 * tid + 2] = az * inv;
        out[ob + 4 * tid + 3] = aw * inv;
        if (tid == 0) out[ob + 512] = ipn;
    } else {
        size_t rb = (size_t)row * PH;
        out[ob + tid]       = hc0[rb + tid];
        out[ob + 128 + tid] = hh0[rb + tid];
        out[ob + 256 + tid] = hc1[rb + tid];
        out[ob + 384 + tid] = hh1[rb + tid];
        if (tid == 0) out[ob + 512] = ipold[row];
    }
}

// ---------------- host launcher ----------------
extern "C" void kernel_launch(void* const* d_in, const int* in_sizes, int n_in,
                              void* d_out, int out_size)
{
    const float* emb  = (const float*)d_in[0];
    const float* hc0  = (const float*)d_in[1];
    const float* hh0  = (const float*)d_in[2];
    const float* hc1  = (const float*)d_in[3];
    const float* hh1  = (const float*)d_in[4];
    const float* ip   = (const float*)d_in[5];
    const float* Wi0  = (const float*)d_in[6];
    const float* Wh0  = (const float*)d_in[7];
    const float* b0   = (const float*)d_in[8];
    const float* Wi1  = (const float*)d_in[9];
    const float* Wh1  = (const float*)d_in[10];
    const float* b1   = (const float*)d_in[11];
    const float* Wr   = (const float*)d_in[12];
    const float* br   = (const float*)d_in[13];
    const float* Wb   = (const float*)d_in[14];
    const float* bb   = (const float*)d_in[15];
    const int* ti     = (const int*)d_in[16];
    const int* fi     = (const int*)d_in[17];
    const int* ri     = (const int*)d_in[18];
    const int* exi    = (const int*)d_in[19];
    const int* rai    = (const int*)d_in[20];
    const int* slim   = (const int*)d_in[21];
    const int* cstep  = (n_in >= 23) ? (const int*)d_in[22] : nullptr;
    float* out = (float*)d_out;

    float *contrib, *WT0, *WT1, *bP0, *bP1;
    cudaGetSymbolAddress((void**)&contrib, g_contrib);
    cudaGetSymbolAddress((void**)&WT0,     g_WT0);
    cudaGetSymbolAddress((void**)&WT1,     g_WT1);
    cudaGetSymbolAddress((void**)&bP0,     g_bP0);
    cudaGetSymbolAddress((void**)&bP1,     g_bP1);

    cudaFuncSetAttribute(ip_lstm_mma,
                         cudaFuncAttributeMaxDynamicSharedMemorySize, SMEM_TOTAL_GEMM);

    // exactly five kernel launches before gemm0 (ncu -s 5 -c 1 → gemm0); no memsets
    ip_permW<<<512, 256>>>(Wi0, Wh0, b0, WT0, bP0);                   // 0
    ip_permW<<<512, 256>>>(Wi1, Wh1, b1, WT1, bP1);                   // 1
    ip_zcnt<<<64, 256>>>();                                           // 2
    ip_count<<<PM / 256, 256>>>(ti, fi, ri);                          // 3
    ip_pad<<<1, 32>>>();                                              // 4

    dim3 ggrid(4, PM / 128);
    // Layer 0 (launch 5: ncu target)
    ip_lstm_mma<<<ggrid, 256, SMEM_TOTAL_GEMM>>>(
        emb, PH, hh0, PH, hc0, WT0, bP0, contrib + 0, contrib + 128);
    // Layer 1
    ip_lstm_mma<<<ggrid, 256, SMEM_TOTAL_GEMM>>>(
        contrib + 128, PG4, hh1, PH, hc1, WT1, bP1, contrib + 256, contrib + 384);

    ip_scan<<<PB, 512>>>();

    ip_mask<<<dim3(PB, 2), 128>>>(hc0, hh0, hc1, hh1, exi, rai);

    ip_decision<<<PM / 8, 256>>>(Wr, br, Wb, bb, ip, ti, fi, ri, exi, rai,
                                 slim, cstep, 5);

    ip_gather<<<PM, 128>>>(hc0, hh0, hc1, hh1, ip, slim, cstep, 5, out);
}

// round 11
// speedup vs baseline: 1.1148x; 1.1148x over previous
#include <cuda_runtime.h>
#include <math.h>
#include <stdint.h>

// Problem constants
#define PB 32
#define PN 2048
#define PH 128
#define PG4 512
#define PM (PB * PN)   // 65536 rows
#define PK 256         // combined K = [X | H]

// ---------------- device scratch (no allocations allowed) ----------------
__device__ float g_contrib[(size_t)PM * PG4];   // [c0 | h0 | c1 | h1] per row
__device__ float g_WT0[PG4 * PK];               // B operand, layer0: [n][k], tf32-rounded
__device__ float g_WT1[PG4 * PK];               // layer1
__device__ float g_bP0[PG4];
__device__ float g_bP1[PG4];
__device__ float g_logits[(size_t)PM * 4];      // per-row [r0, r1, b0, b1]
__device__ float g_ipnew[PM];
__device__ int   g_cnt[PM];                     // incoming-edge counts per target
__device__ int   g_off[PM];                     // CSR offsets
__device__ int   g_cur[PM];                     // fill cursors
__device__ int   g_esrc[3 * PM];                // edge source rows
__device__ float g_ew[3 * PM];                  // edge weights

// ---------------- helpers ----------------
__device__ __forceinline__ uint32_t smem_u32(const void* p) {
    uint32_t a;
    asm("{ .reg .u64 t; cvta.to.shared.u64 t, %1; cvt.u32.u64 %0, t; }" : "=r"(a) : "l"(p));
    return a;
}
__device__ __forceinline__ uint32_t f2tf32(float x) {
    uint32_t r;
    asm("cvt.rna.tf32.f32 %0, %1;" : "=r"(r) : "f"(x));
    return r;
}
__device__ __forceinline__ void mma8(float* d, const uint32_t* a, const uint32_t* b) {
    asm volatile(
        "mma.sync.aligned.m16n8k8.row.col.f32.tf32.tf32.f32 "
        "{%0,%1,%2,%3}, {%4,%5,%6,%7}, {%8,%9}, {%0,%1,%2,%3};"
        : "+f"(d[0]), "+f"(d[1]), "+f"(d[2]), "+f"(d[3])
        : "r"(a[0]), "r"(a[1]), "r"(a[2]), "r"(a[3]), "r"(b[0]), "r"(b[1]));
}
__device__ __forceinline__ void red4(float* p, float a, float b, float c, float d) {
    asm volatile("red.global.add.v4.f32 [%0], {%1,%2,%3,%4};"
                 :: "l"(p), "f"(a), "f"(b), "f"(c), "f"(d) : "memory");
}
#define CP_ASYNC16(s, g) asm volatile("cp.async.cg.shared.global [%0], [%1], 16;" :: "r"(s), "l"(g))
#define CP_COMMIT() asm volatile("cp.async.commit_group;" ::: "memory")
#define CP_WAIT0() asm volatile("cp.async.wait_group 0;" ::: "memory")
#define CP_WAIT1() asm volatile("cp.async.wait_group 1;" ::: "memory")

__device__ __forceinline__ float sigf(float x) {
    return __fdividef(1.0f, 1.0f + __expf(-x));
}
__device__ __forceinline__ float tanhf_f(float x) {
    float xc = fminf(fmaxf(x, -15.0f), 15.0f);
    float e = __expf(2.0f * xc);
    return __fdividef(e - 1.0f, e + 1.0f);
}

// ---------------- weight prep (bias merged in) ----------------
// Gate-column permutation: for unit u (0..127), gate g (i=0,f=1,g=2,o=3):
//   c(u,g) = (u>>2)*16 + (u&3)*2 + (g&1) + (g>>1)*8
__device__ __forceinline__ int perm_oc(int n) {
    int blk = n >> 4, w = n & 15;
    int ghi = w >> 3, pos = (w & 7) >> 1, glo = w & 1;
    int u = blk * 4 + pos;
    int g = ghi * 2 + glo;
    return g * 128 + u;
}
__global__ void ip_permW(const float* __restrict__ Wi, const float* __restrict__ Wh,
                         const float* __restrict__ bsrc,
                         float* __restrict__ WT, float* __restrict__ bdst)
{
    int t = blockIdx.x * 256 + threadIdx.x;    // [0, 512*256)
    int n = t >> 8;
    int k = t & 255;
    int oc = perm_oc(n);
    float w = (k < 128) ? Wi[k * PG4 + oc] : Wh[(k - 128) * PG4 + oc];
    WT[t] = __uint_as_float(f2tf32(w));
    if (k == 0) bdst[n] = bsrc[oc];
}

// ---------------- zero cnt + logits ----------------
__global__ void ip_zero()
{
    int i = blockIdx.x * 256 + threadIdx.x;    // grid 320: 16384 cnt-int4 + 65536 logit-float4
    if (i < 16384) ((int4*)g_cnt)[i] = make_int4(0, 0, 0, 0);
    else ((float4*)g_logits)[i - 16384] = make_float4(0.f, 0.f, 0.f, 0.f);
}
__global__ void ip_count(const int* __restrict__ ti, const int* __restrict__ fi,
                         const int* __restrict__ ri)
{
    int s = blockIdx.x * 256 + threadIdx.x;
    int bb = (s >> 11) << 11;
    atomicAdd(&g_cnt[bb + ri[s]], 1);
    atomicAdd(&g_cnt[bb + ti[s]], 1);
    atomicAdd(&g_cnt[bb + fi[s]], 1);
}
__global__ void ip_pad() {}

// ---------------- CSR: per-batch exclusive scan of counts; zero ipnew ------
__global__ __launch_bounds__(512) void ip_scan()
{
    __shared__ int part[512];
    int b = blockIdx.x;
    int t = threadIdx.x;
    int base = b << 11;

    int c0 = g_cnt[base + 4 * t + 0];
    int c1 = g_cnt[base + 4 * t + 1];
    int c2 = g_cnt[base + 4 * t + 2];
    int c3 = g_cnt[base + 4 * t + 3];
    int l0 = c0, l1 = l0 + c1, l2 = l1 + c2, l3 = l2 + c3;
    part[t] = l3;
    __syncthreads();
    for (int o = 1; o < 512; o <<= 1) {
        int v = (t >= o) ? part[t - o] : 0;
        __syncthreads();
        part[t] += v;
        __syncthreads();
    }
    int ex = (t == 0) ? 0 : part[t - 1];
    int gb = b * 6144 + ex;
    g_off[base + 4 * t + 0] = gb;
    g_off[base + 4 * t + 1] = gb + l0;
    g_off[base + 4 * t + 2] = gb + l1;
    g_off[base + 4 * t + 3] = gb + l2;
    g_cur[base + 4 * t + 0] = gb;
    g_cur[base + 4 * t + 1] = gb + l0;
    g_cur[base + 4 * t + 2] = gb + l1;
    g_cur[base + 4 * t + 3] = gb + l2;
    g_ipnew[base + 4 * t + 0] = 0.0f;
    g_ipnew[base + 4 * t + 1] = 0.0f;
    g_ipnew[base + 4 * t + 2] = 0.0f;
    g_ipnew[base + 4 * t + 3] = 0.0f;
}

// ---------------- tf32 mma.sync GEMM + fused LSTM + logit epilogue ----------
// Mainloop = round-9 proven config: 128x128 CTA tile, 8 warps (4M x 2N),
// 3-stage all-cp.async pipeline, LDS fragment loads, A_STRIDE 36.
#define A_STRIDE 36
#define HALF_STAGE (128 * A_STRIDE * 4)          // 18432
#define STAGE_BYTES (2 * HALF_STAGE)             // 36864
#define SMEM_TOTAL_GEMM (3 * STAGE_BYTES)        // 110592

__global__ __launch_bounds__(256, 2) void ip_lstm_mma(
    const float* __restrict__ X, int xs,
    const float* __restrict__ Hp, int hs,
    const float* __restrict__ Cold,
    const float* __restrict__ WT, const float* __restrict__ bP,
    const float* __restrict__ Wr, const float* __restrict__ Wb, int cbase,
    float* __restrict__ outC, float* __restrict__ outH)
{
    extern __shared__ char smem[];

    int tid = threadIdx.x;
    int wid = tid >> 5, lane = tid & 31;
    int wm = wid & 3, wn = wid >> 2;
    int row0 = blockIdx.y * 128;
    int col0 = blockIdx.x * 128;

    float acc[2][8][4];
#pragma unroll
    for (int mt = 0; mt < 2; mt++)
#pragma unroll
        for (int nt = 0; nt < 8; nt++)
#pragma unroll
            for (int q = 0; q < 4; q++) acc[mt][nt][q] = 0.0f;

    float bI[4], bF[4], bG[4], bO[4];
#pragma unroll
    for (int p = 0; p < 4; p++) {
        int c0 = col0 + wn * 64 + p * 16 + (lane & 3) * 2;
        bI[p] = bP[c0];     bF[p] = bP[c0 + 1];
        bG[p] = bP[c0 + 8]; bO[p] = bP[c0 + 9];
    }

    auto prefetch = [&](int c) {
        const float* Asrc = (c < 4) ? X : Hp;
        int astr = (c < 4) ? xs : hs;
        int ka = (c & 3) * 32;
        int kb = c * 32;
        char* As = smem + (c % 3) * STAGE_BYTES;
        char* Bs = As + HALF_STAGE;
#pragma unroll
        for (int j = 0; j < 4; j++) {
            int fid = j * 256 + tid;
            int r = fid >> 3, q = fid & 7;
            CP_ASYNC16(smem_u32(As + r * (A_STRIDE * 4) + q * 16),
                       Asrc + (size_t)(row0 + r) * astr + ka + q * 4);
            CP_ASYNC16(smem_u32(Bs + r * (A_STRIDE * 4) + q * 16),
                       WT + (size_t)(col0 + r) * PK + kb + q * 4);
        }
    };

    prefetch(0); CP_COMMIT();
    prefetch(1); CP_COMMIT();
    CP_WAIT1();
    __syncthreads();

    int a_base = (wm * 32 + (lane >> 2)) * A_STRIDE;
    int b_base = (wn * 64 + (lane >> 2)) * A_STRIDE;
    int kc = lane & 3;

#pragma unroll 1
    for (int ch = 0; ch < 8; ch++) {
        uint32_t* Abuf = (uint32_t*)(smem + (ch % 3) * STAGE_BYTES);
        uint32_t* Bbuf = (uint32_t*)(smem + (ch % 3) * STAGE_BYTES + HALF_STAGE);
#pragma unroll
        for (int ks = 0; ks < 4; ks++) {
            int kk = ks * 8 + kc;
            uint32_t a[2][4];
#pragma unroll
            for (int mt = 0; mt < 2; mt++) {
                int rb = a_base + mt * 16 * A_STRIDE;
                a[mt][0] = Abuf[rb + kk];
                a[mt][1] = Abuf[rb + 8 * A_STRIDE + kk];
                a[mt][2] = Abuf[rb + kk + 4];
                a[mt][3] = Abuf[rb + 8 * A_STRIDE + kk + 4];
            }
            uint32_t b[8][2];
#pragma unroll
            for (int nt = 0; nt < 8; nt++) {
                int nb = b_base + nt * 8 * A_STRIDE;
                b[nt][0] = Bbuf[nb + kk];
                b[nt][1] = Bbuf[nb + kk + 4];
            }
#pragma unroll
            for (int mt = 0; mt < 2; mt++)
#pragma unroll
                for (int nt = 0; nt < 8; nt++)
                    mma8(acc[mt][nt], a[mt], b[nt]);
        }

        if (ch < 7) {
            if (ch < 6) {
                prefetch(ch + 2);
                CP_COMMIT();
                CP_WAIT1();
            } else {
                CP_WAIT0();
            }
            __syncthreads();
        }
    }

    // ---- fused LSTM epilogue + per-row logit partials ----
    const float2* Wr2 = (const float2*)Wr;
    const float2* Wb2 = (const float2*)Wb;
#pragma unroll
    for (int mt = 0; mt < 2; mt++) {
        int r = row0 + wm * 32 + mt * 16 + (lane >> 2);
        float s0a = 0.f, s1a = 0.f, s2a = 0.f, s3a = 0.f;   // row r
        float s0b = 0.f, s1b = 0.f, s2b = 0.f, s3b = 0.f;   // row r+8
#pragma unroll
        for (int p = 0; p < 4; p++) {
            int u = (col0 >> 2) + wn * 16 + p * 4 + (lane & 3);
            float co0 = Cold[(size_t)r * PH + u];
            float co1 = Cold[(size_t)(r + 8) * PH + u];
            float iv = acc[mt][2 * p][0] + bI[p];
            float fv = acc[mt][2 * p][1] + bF[p];
            float gv = acc[mt][2 * p + 1][0] + bG[p];
            float ov = acc[mt][2 * p + 1][1] + bO[p];
            float cn0 = sigf(fv) * co0 + sigf(iv) * tanhf_f(gv);
            float hn0 = sigf(ov) * tanhf_f(cn0);
            float iv1 = acc[mt][2 * p][2] + bI[p];
            float fv1 = acc[mt][2 * p][3] + bF[p];
            float gv1 = acc[mt][2 * p + 1][2] + bG[p];
            float ov1 = acc[mt][2 * p + 1][3] + bO[p];
            float cn1 = sigf(fv1) * co1 + sigf(iv1) * tanhf_f(gv1);
            float hn1 = sigf(ov1) * tanhf_f(cn1);

            outC[(size_t)r * PG4 + u] = cn0;
            outH[(size_t)r * PG4 + u] = hn0;
            outC[(size_t)(r + 8) * PG4 + u] = cn1;
            outH[(size_t)(r + 8) * PG4 + u] = hn1;

            // logit partials: concat positions pc (c-quarter), ph (h-quarter)
            int pc = cbase + u, ph = pc + 128;
            float2 wrc = Wr2[pc], wrh = Wr2[ph];
            float2 wbc = Wb2[pc], wbh = Wb2[ph];
            s0a = fmaf(cn0, wrc.x, fmaf(hn0, wrh.x, s0a));
            s1a = fmaf(cn0, wrc.y, fmaf(hn0, wrh.y, s1a));
            s2a = fmaf(cn0, wbc.x, fmaf(hn0, wbh.x, s2a));
            s3a = fmaf(cn0, wbc.y, fmaf(hn0, wbh.y, s3a));
            s0b = fmaf(cn1, wrc.x, fmaf(hn1, wrh.x, s0b));
            s1b = fmaf(cn1, wrc.y, fmaf(hn1, wrh.y, s1b));
            s2b = fmaf(cn1, wbc.x, fmaf(hn1, wbh.x, s2b));
            s3b = fmaf(cn1, wbc.y, fmaf(hn1, wbh.y, s3b));
        }
        // reduce across the 4 lanes sharing each row (lane&3 axis)
#pragma unroll
        for (int o = 1; o <= 2; o <<= 1) {
            s0a += __shfl_xor_sync(0xffffffffu, s0a, o);
            s1a += __shfl_xor_sync(0xffffffffu, s1a, o);
            s2a += __shfl_xor_sync(0xffffffffu, s2a, o);
            s3a += __shfl_xor_sync(0xffffffffu, s3a, o);
            s0b += __shfl_xor_sync(0xffffffffu, s0b, o);
            s1b += __shfl_xor_sync(0xffffffffu, s1b, o);
            s2b += __shfl_xor_sync(0xffffffffu, s2b, o);
            s3b += __shfl_xor_sync(0xffffffffu, s3b, o);
        }
        if ((lane & 3) == 0) {
            red4(&g_logits[(size_t)r * 4], s0a, s1a, s2a, s3a);
            red4(&g_logits[(size_t)(r + 8) * 4], s0b, s1b, s2b, s3b);
        }
    }
}

// ---------------- mask exit/raise nodes: contrib <- old state ----------------
__global__ void ip_mask(const float* __restrict__ hc0, const float* __restrict__ hh0,
                        const float* __restrict__ hc1, const float* __restrict__ hh1,
                        const int* __restrict__ exi, const int* __restrict__ rai)
{
    int b = blockIdx.x;
    int node = blockIdx.y ? rai[b] : exi[b];
    int tid = threadIdx.x;  // 128
    size_t r = (size_t)b * PN + node;
    float* dst = g_contrib + r * PG4;
    size_t rb = r * PH;
    dst[tid]       = hc0[rb + tid];
    dst[128 + tid] = hh0[rb + tid];
    dst[256 + tid] = hc1[rb + tid];
    dst[384 + tid] = hh1[rb + tid];
}

// ---------------- recompute logits for masked rows from (masked) contrib -----
__global__ void ip_fixlog(const int* __restrict__ exi, const int* __restrict__ rai,
                          const float* __restrict__ Wr, const float* __restrict__ Wb)
{
    int b = blockIdx.x;
    int node = blockIdx.y ? rai[b] : exi[b];
    int lane = threadIdx.x;  // 32
    int row = (b << 11) + node;
    const float* crow = g_contrib + (size_t)row * PG4;

    float r0 = 0.f, r1 = 0.f, q0 = 0.f, q1 = 0.f;
#pragma unroll
    for (int t2 = 0; t2 < 4; t2++) {
        int cb = lane * 4 + t2 * 128;
        float4 v = *(const float4*)&crow[cb];
        float vv[4] = {v.x, v.y, v.z, v.w};
#pragma unroll
        for (int q = 0; q < 4; q++) {
            float w = vv[q];
            int c2 = (cb + q) * 2;
            r0 = fmaf(w, Wr[c2 + 0], r0);
            r1 = fmaf(w, Wr[c2 + 1], r1);
            q0 = fmaf(w, Wb[c2 + 0], q0);
            q1 = fmaf(w, Wb[c2 + 1], q1);
        }
    }
#pragma unroll
    for (int o = 16; o > 0; o >>= 1) {
        r0 += __shfl_xor_sync(0xffffffffu, r0, o);
        r1 += __shfl_xor_sync(0xffffffffu, r1, o);
        q0 += __shfl_xor_sync(0xffffffffu, q0, o);
        q1 += __shfl_xor_sync(0xffffffffu, q1, o);
    }
    if (lane == 0)
        ((float4*)g_logits)[row] = make_float4(r0, r1, q0, q1);
}

// ---------------- edge weights from logits + CSR fill ----------------
__global__ __launch_bounds__(256) void ip_edges(
    const float* __restrict__ brs, const float* __restrict__ bbs,
    const float* __restrict__ ipin,
    const int* __restrict__ ti, const int* __restrict__ fi, const int* __restrict__ ri,
    const int* __restrict__ exi, const int* __restrict__ rai,
    const int* __restrict__ slim, const int* __restrict__ cstep, int cs_fallback)
{
    int row = blockIdx.x * 256 + threadIdx.x;
    int b = row >> 11, n = row & 2047;

    int cs = cstep ? cstep[0] : cs_fallback;
    if (cs >= slim[b]) return;

    float4 L = ((const float4*)g_logits)[row];
    float lr = (L.x + brs[0]) - (L.y + brs[1]);
    float p_raise = sigf(lr);
    float p_no = 1.0f - p_raise;
    if (n == exi[b] || n == rai[b]) { p_raise = 0.0f; p_no = 1.0f; }
    float lb = (L.z + bbs[0]) - (L.w + bbs[1]);
    float pb0 = sigf(lb);
    float pb1 = 1.0f - pb0;

    float ipv = ipin[row];
    float wr_ = p_raise * ipv;
    float wt_ = p_no * pb0 * ipv;
    float wf_ = p_no * pb1 * ipv;

    int bb2 = b << 11;
    int tr = bb2 + ri[row], tt = bb2 + ti[row], tf = bb2 + fi[row];
    atomicAdd(&g_ipnew[tr], wr_);
    atomicAdd(&g_ipnew[tt], wt_);
    atomicAdd(&g_ipnew[tf], wf_);
    if (wr_ != 0.0f) {
        int s = atomicAdd(&g_cur[tr], 1);
        g_esrc[s] = row; g_ew[s] = wr_;
    }
    if (wt_ != 0.0f) {
        int s = atomicAdd(&g_cur[tt], 1);
        g_esrc[s] = row; g_ew[s] = wt_;
    }
    if (wf_ != 0.0f) {
        int s = atomicAdd(&g_cur[tf], 1);
        g_esrc[s] = row; g_ew[s] = wf_;
    }
}

// ---------------- gather + finalize ----------------
__global__ __launch_bounds__(128) void ip_gather(
    const float* __restrict__ hc0, const float* __restrict__ hh0,
    const float* __restrict__ hc1, const float* __restrict__ hh1,
    const float* __restrict__ ipold, const int* __restrict__ slim,
    const int* __restrict__ cstep, int cs_fallback, float* __restrict__ out)
{
    int row = blockIdx.x;
    int tid = threadIdx.x;  // 128
    int b = row >> 11;
    int cs = cstep ? cstep[0] : cs_fallback;
    bool nd = cs < slim[b];
    size_t ob = (size_t)row * 513;
    if (nd) {
        int s = g_off[row], e = g_cur[row];
        const float4* cb = (const float4*)g_contrib;
        float ax = 0.f, ay = 0.f, az = 0.f, aw = 0.f;
        for (int i = s; i < e; i++) {
            float w = g_ew[i];
            int src = g_esrc[i];
            float4 v = cb[(size_t)src * 128 + tid];
            ax = fmaf(w, v.x, ax); ay = fmaf(w, v.y, ay);
            az = fmaf(w, v.z, az); aw = fmaf(w, v.w, aw);
        }
        float ipn = g_ipnew[row];
        float inv = __fdividef(1.0f, ipn + 1e-7f);
        out[ob + 4 * tid + 0] = ax * inv;
        out[ob + 4 * tid + 1] = ay * inv;
        out[ob + 4 * tid + 2] = az * inv;
        out[ob + 4 * tid + 3] = aw * inv;
        if (tid == 0) out[ob + 512] = ipn;
    } else {
        size_t rb = (size_t)row * PH;
        out[ob + tid]       = hc0[rb + tid];
        out[ob + 128 + tid] = hh0[rb + tid];
        out[ob + 256 + tid] = hc1[rb + tid];
        out[ob + 384 + tid] = hh1[rb + tid];
        if (tid == 0) out[ob + 512] = ipold[row];
    }
}

// ---------------- host launcher ----------------
extern "C" void kernel_launch(void* const* d_in, const int* in_sizes, int n_in,
                              void* d_out, int out_size)
{
    const float* emb  = (const float*)d_in[0];
    const float* hc0  = (const float*)d_in[1];
    const float* hh0  = (const float*)d_in[2];
    const float* hc1  = (const float*)d_in[3];
    const float* hh1  = (const float*)d_in[4];
    const float* ip   = (const float*)d_in[5];
    const float* Wi0  = (const float*)d_in[6];
    const float* Wh0  = (const float*)d_in[7];
    const float* b0   = (const float*)d_in[8];
    const float* Wi1  = (const float*)d_in[9];
    const float* Wh1  = (const float*)d_in[10];
    const float* b1   = (const float*)d_in[11];
    const float* Wr   = (const float*)d_in[12];
    const float* br   = (const float*)d_in[13];
    const float* Wb   = (const float*)d_in[14];
    const float* bb   = (const float*)d_in[15];
    const int* ti     = (const int*)d_in[16];
    const int* fi     = (const int*)d_in[17];
    const int* ri     = (const int*)d_in[18];
    const int* exi    = (const int*)d_in[19];
    const int* rai    = (const int*)d_in[20];
    const int* slim   = (const int*)d_in[21];
    const int* cstep  = (n_in >= 23) ? (const int*)d_in[22] : nullptr;
    float* out = (float*)d_out;

    float *contrib, *WT0, *WT1, *bP0, *bP1;
    cudaGetSymbolAddress((void**)&contrib, g_contrib);
    cudaGetSymbolAddress((void**)&WT0,     g_WT0);
    cudaGetSymbolAddress((void**)&WT1,     g_WT1);
    cudaGetSymbolAddress((void**)&bP0,     g_bP0);
    cudaGetSymbolAddress((void**)&bP1,     g_bP1);

    cudaFuncSetAttribute(ip_lstm_mma,
                         cudaFuncAttributeMaxDynamicSharedMemorySize, SMEM_TOTAL_GEMM);

    ip_permW<<<512, 256>>>(Wi0, Wh0, b0, WT0, bP0);
    ip_permW<<<512, 256>>>(Wi1, Wh1, b1, WT1, bP1);
    ip_zero<<<320, 256>>>();
    ip_count<<<PM / 256, 256>>>(ti, fi, ri);
    ip_pad<<<1, 32>>>();

    dim3 ggrid(4, PM / 128);
    // Layer 0: cbase 0 (c0 at 0, h0 at 128)
    ip_lstm_mma<<<ggrid, 256, SMEM_TOTAL_GEMM>>>(
        emb, PH, hh0, PH, hc0, WT0, bP0, Wr, Wb, 0, contrib + 0, contrib + 128);
    // Layer 1: cbase 256 (c1 at 256, h1 at 384); input h0n from contrib (stride 512)
    ip_lstm_mma<<<ggrid, 256, SMEM_TOTAL_GEMM>>>(
        contrib + 128, PG4, hh1, PH, hc1, WT1, bP1, Wr, Wb, 256, contrib + 256, contrib + 384);

    ip_scan<<<PB, 512>>>();

    ip_mask<<<dim3(PB, 2), 128>>>(hc0, hh0, hc1, hh1, exi, rai);

    ip_fixlog<<<dim3(PB, 2), 32>>>(exi, rai, Wr, Wb);

    ip_edges<<<PM / 256, 256>>>(br, bb, ip, ti, fi, ri, exi, rai, slim, cstep, 5);

    ip_gather<<<PM, 128>>>(hc0, hh0, hc1, hh1, ip, slim, cstep, 5, out);
}

// round 12
// speedup vs baseline: 1.2786x; 1.1470x over previous
#include <cuda_runtime.h>
#include <cuda_fp16.h>
#include <math.h>
#include <stdint.h>

// Problem constants
#define PB 32
#define PN 2048
#define PH 128
#define PG4 512
#define PM (PB * PN)   // 65536 rows
#define PK 256         // combined K = [X | H]

// ---------------- device scratch (no allocations allowed) ----------------
__device__ float  g_contrib[(size_t)PM * PG4];  // [c0 | h0 | c1 | h1] per row (fp32)
__device__ __half g_A0[(size_t)PM * PK];        // layer0 A: [emb | hh0] half
__device__ __half g_A1[(size_t)PM * PK];        // layer1 A: [h0n | hh1] half
__device__ __half g_WT0h[PG4 * PK];             // layer0 weights [n][k] half
__device__ __half g_WT1h[PG4 * PK];             // layer1 weights half
__device__ float  g_bP0[PG4];
__device__ float  g_bP1[PG4];
__device__ float  g_logits[(size_t)PM * 4];     // per-row [r0, r1, b0, b1]
__device__ float  g_ipnew[PM];
__device__ int    g_cnt[PM];                    // zero-init at load; scan re-zeroes
__device__ int    g_off[PM];
__device__ int    g_cur[PM];
__device__ int    g_esrc[3 * PM];
__device__ float  g_ew[3 * PM];

// ---------------- helpers ----------------
__device__ __forceinline__ uint32_t smem_u32(const void* p) {
    uint32_t a;
    asm("{ .reg .u64 t; cvta.to.shared.u64 t, %1; cvt.u32.u64 %0, t; }" : "=r"(a) : "l"(p));
    return a;
}
__device__ __forceinline__ void mma16(float* d, const uint32_t* a, const uint32_t* b) {
    asm volatile(
        "mma.sync.aligned.m16n8k16.row.col.f32.f16.f16.f32 "
        "{%0,%1,%2,%3}, {%4,%5,%6,%7}, {%8,%9}, {%0,%1,%2,%3};"
        : "+f"(d[0]), "+f"(d[1]), "+f"(d[2]), "+f"(d[3])
        : "r"(a[0]), "r"(a[1]), "r"(a[2]), "r"(a[3]), "r"(b[0]), "r"(b[1]));
}
__device__ __forceinline__ void red4(float* p, float a, float b, float c, float d) {
    asm volatile("red.global.add.v4.f32 [%0], {%1,%2,%3,%4};"
                 :: "l"(p), "f"(a), "f"(b), "f"(c), "f"(d) : "memory");
}
#define CP_ASYNC16(s, g) asm volatile("cp.async.cg.shared.global [%0], [%1], 16;" :: "r"(s), "l"(g))
#define CP_COMMIT() asm volatile("cp.async.commit_group;" ::: "memory")
#define CP_WAIT0() asm volatile("cp.async.wait_group 0;" ::: "memory")
#define CP_WAIT1() asm volatile("cp.async.wait_group 1;" ::: "memory")

__device__ __forceinline__ float sigf(float x) {
    return __fdividef(1.0f, 1.0f + __expf(-x));
}
__device__ __forceinline__ float tanhf_f(float x) {
    float xc = fminf(fmaxf(x, -15.0f), 15.0f);
    float e = __expf(2.0f * xc);
    return __fdividef(e - 1.0f, e + 1.0f);
}

// ---------------- prelude: pack A operands as half ----------------
// section 0: emb -> g_A0[:,0:128);  1: hh0 -> g_A0[:,128:256);  2: hh1 -> g_A1[:,128:256)
__global__ void ip_cvt16(const float* __restrict__ emb, const float* __restrict__ hh0,
                         const float* __restrict__ hh1)
{
    int i = blockIdx.x * 256 + threadIdx.x;     // [0, PM*PH/4)
    int s = blockIdx.y;
    const float4* src = (const float4*)(s == 0 ? emb : (s == 1 ? hh0 : hh1));
    float4 v = src[i];
    int r = i >> 5, c4 = i & 31;                // 32 float4 per row of 128
    __half2 h0 = __floats2half2_rn(v.x, v.y);
    __half2 h1 = __floats2half2_rn(v.z, v.w);
    __half2* dst = (__half2*)(s == 2 ? g_A1 : g_A0);
    int off = r * 128 + (s == 0 ? 0 : 64) + c4 * 2;
    dst[off] = h0;
    dst[off + 1] = h1;
}

// ---------------- weight prep (half) ----------------
// Gate-column permutation: c(u,g) = (u>>2)*16 + (u&3)*2 + (g&1) + (g>>1)*8
__device__ __forceinline__ int perm_oc(int n) {
    int blk = n >> 4, w = n & 15;
    int ghi = w >> 3, pos = (w & 7) >> 1, glo = w & 1;
    int u = blk * 4 + pos;
    int g = ghi * 2 + glo;
    return g * 128 + u;
}
__global__ void ip_permW(const float* __restrict__ Wi, const float* __restrict__ Wh,
                         const float* __restrict__ bsrc,
                         __half* __restrict__ WT, float* __restrict__ bdst)
{
    int t = blockIdx.x * 256 + threadIdx.x;    // [0, 512*256)
    int n = t >> 8;
    int k = t & 255;
    int oc = perm_oc(n);
    float w = (k < 128) ? Wi[k * PG4 + oc] : Wh[(k - 128) * PG4 + oc];
    WT[t] = __float2half_rn(w);
    if (k == 0) bdst[n] = bsrc[oc];
}

// ---------------- CSR: count incoming edges per target --------------------
__global__ void ip_count(const int* __restrict__ ti, const int* __restrict__ fi,
                         const int* __restrict__ ri)
{
    int s = blockIdx.x * 256 + threadIdx.x;
    int bb = (s >> 11) << 11;
    atomicAdd(&g_cnt[bb + ri[s]], 1);
    atomicAdd(&g_cnt[bb + ti[s]], 1);
    atomicAdd(&g_cnt[bb + fi[s]], 1);
}

// ---------------- CSR scan; re-zeroes g_cnt; zeroes ipnew ------------------
__global__ __launch_bounds__(512) void ip_scan()
{
    __shared__ int part[512];
    int b = blockIdx.x;
    int t = threadIdx.x;
    int base = b << 11;

    int c0 = g_cnt[base + 4 * t + 0];
    int c1 = g_cnt[base + 4 * t + 1];
    int c2 = g_cnt[base + 4 * t + 2];
    int c3 = g_cnt[base + 4 * t + 3];
    // self-clean for next graph replay
    g_cnt[base + 4 * t + 0] = 0;
    g_cnt[base + 4 * t + 1] = 0;
    g_cnt[base + 4 * t + 2] = 0;
    g_cnt[base + 4 * t + 3] = 0;
    int l0 = c0, l1 = l0 + c1, l2 = l1 + c2, l3 = l2 + c3;
    part[t] = l3;
    __syncthreads();
    for (int o = 1; o < 512; o <<= 1) {
        int v = (t >= o) ? part[t - o] : 0;
        __syncthreads();
        part[t] += v;
        __syncthreads();
    }
    int ex = (t == 0) ? 0 : part[t - 1];
    int gb = b * 6144 + ex;
    g_off[base + 4 * t + 0] = gb;
    g_off[base + 4 * t + 1] = gb + l0;
    g_off[base + 4 * t + 2] = gb + l1;
    g_off[base + 4 * t + 3] = gb + l2;
    g_cur[base + 4 * t + 0] = gb;
    g_cur[base + 4 * t + 1] = gb + l0;
    g_cur[base + 4 * t + 2] = gb + l1;
    g_cur[base + 4 * t + 3] = gb + l2;
    g_ipnew[base + 4 * t + 0] = 0.0f;
    g_ipnew[base + 4 * t + 1] = 0.0f;
    g_ipnew[base + 4 * t + 2] = 0.0f;
    g_ipnew[base + 4 * t + 3] = 0.0f;
}

// ---------------- fp16 mma.sync GEMM + fused LSTM + logit epilogue ----------
// CTA 128x128, 8 warps (4M x 2N), K=256 in 8 chunks of 32 halves (64B/row data,
// padded to 80B). 3-stage all-cp.async pipeline. A packed [X|H] half, stride 256.
#define A_STRIDE 20                               // floats per row (80 B)
#define HALF_STAGE (128 * A_STRIDE * 4)           // 10240
#define STAGE_BYTES (2 * HALF_STAGE)              // 20480
#define SMEM_TOTAL_GEMM (3 * STAGE_BYTES)         // 61440

__global__ __launch_bounds__(256, 2) void ip_lstm_mma(
    const __half* __restrict__ Ah,                // [M][256] packed half
    const float* __restrict__ Cold,
    const __half* __restrict__ WT, const float* __restrict__ bP,
    const float* __restrict__ Wr, const float* __restrict__ Wb, int cbase,
    float* __restrict__ outC, float* __restrict__ outH,
    __half* __restrict__ outH16)                  // layer0: g_A1 base; layer1: null
{
    extern __shared__ char smem[];

    int tid = threadIdx.x;
    int wid = tid >> 5, lane = tid & 31;
    int wm = wid & 3, wn = wid >> 2;
    int row0 = blockIdx.y * 128;
    int col0 = blockIdx.x * 128;

    float acc[2][8][4];
#pragma unroll
    for (int mt = 0; mt < 2; mt++)
#pragma unroll
        for (int nt = 0; nt < 8; nt++)
#pragma unroll
            for (int q = 0; q < 4; q++) acc[mt][nt][q] = 0.0f;

    float bI[4], bF[4], bG[4], bO[4];
#pragma unroll
    for (int p = 0; p < 4; p++) {
        int c0 = col0 + wn * 64 + p * 16 + (lane & 3) * 2;
        bI[p] = bP[c0];     bF[p] = bP[c0 + 1];
        bG[p] = bP[c0 + 8]; bO[p] = bP[c0 + 9];
    }

    // 16B-unit loads: A tile 128 rows x 64B = 512 units; same for B
    auto prefetch = [&](int c) {
        int kh = c * 32;                          // k offset in halves
        char* As = smem + (c % 3) * STAGE_BYTES;
        char* Bs = As + HALF_STAGE;
#pragma unroll
        for (int j = 0; j < 2; j++) {
            int fid = j * 256 + tid;              // [0,512)
            int r = fid >> 2, q = fid & 3;
            CP_ASYNC16(smem_u32(As + r * 80 + q * 16),
                       Ah + (size_t)(row0 + r) * PK + kh + q * 8);
            CP_ASYNC16(smem_u32(Bs + r * 80 + q * 16),
                       WT + (size_t)(col0 + r) * PK + kh + q * 8);
        }
    };

    prefetch(0); CP_COMMIT();
    prefetch(1); CP_COMMIT();
    CP_WAIT1();
    __syncthreads();

    int a_base = (wm * 32 + (lane >> 2)) * A_STRIDE;
    int b_base = (wn * 64 + (lane >> 2)) * A_STRIDE;
    int kc = lane & 3;

#pragma unroll 1
    for (int ch = 0; ch < 8; ch++) {
        uint32_t* Abuf = (uint32_t*)(smem + (ch % 3) * STAGE_BYTES);
        uint32_t* Bbuf = (uint32_t*)(smem + (ch % 3) * STAGE_BYTES + HALF_STAGE);
#pragma unroll
        for (int ks = 0; ks < 2; ks++) {          // 2 x k16 per 32-half chunk
            int kk = ks * 8 + kc;
            uint32_t a[2][4];
#pragma unroll
            for (int mt = 0; mt < 2; mt++) {
                int rb = a_base + mt * 16 * A_STRIDE;
                a[mt][0] = Abuf[rb + kk];                   // (r,   k pair)
                a[mt][1] = Abuf[rb + 8 * A_STRIDE + kk];    // (r+8, k pair)
                a[mt][2] = Abuf[rb + kk + 4];               // (r,   k+8 pair)
                a[mt][3] = Abuf[rb + 8 * A_STRIDE + kk + 4];
            }
            uint32_t b[8][2];
#pragma unroll
            for (int nt = 0; nt < 8; nt++) {
                int nb = b_base + nt * 8 * A_STRIDE;
                b[nt][0] = Bbuf[nb + kk];
                b[nt][1] = Bbuf[nb + kk + 4];
            }
#pragma unroll
            for (int mt = 0; mt < 2; mt++)
#pragma unroll
                for (int nt = 0; nt < 8; nt++)
                    mma16(acc[mt][nt], a[mt], b[nt]);
        }

        if (ch < 7) {
            if (ch < 6) {
                prefetch(ch + 2);
                CP_COMMIT();
                CP_WAIT1();
            } else {
                CP_WAIT0();
            }
            __syncthreads();
        }
    }

    // ---- fused LSTM epilogue + per-row logit partials ----
    const float2* Wr2 = (const float2*)Wr;
    const float2* Wb2 = (const float2*)Wb;
#pragma unroll
    for (int mt = 0; mt < 2; mt++) {
        int r = row0 + wm * 32 + mt * 16 + (lane >> 2);
        float s0a = 0.f, s1a = 0.f, s2a = 0.f, s3a = 0.f;
        float s0b = 0.f, s1b = 0.f, s2b = 0.f, s3b = 0.f;
#pragma unroll
        for (int p = 0; p < 4; p++) {
            int u = (col0 >> 2) + wn * 16 + p * 4 + (lane & 3);
            float co0 = Cold[(size_t)r * PH + u];
            float co1 = Cold[(size_t)(r + 8) * PH + u];
            float iv = acc[mt][2 * p][0] + bI[p];
            float fv = acc[mt][2 * p][1] + bF[p];
            float gv = acc[mt][2 * p + 1][0] + bG[p];
            float ov = acc[mt][2 * p + 1][1] + bO[p];
            float cn0 = sigf(fv) * co0 + sigf(iv) * tanhf_f(gv);
            float hn0 = sigf(ov) * tanhf_f(cn0);
            float iv1 = acc[mt][2 * p][2] + bI[p];
            float fv1 = acc[mt][2 * p][3] + bF[p];
            float gv1 = acc[mt][2 * p + 1][2] + bG[p];
            float ov1 = acc[mt][2 * p + 1][3] + bO[p];
            float cn1 = sigf(fv1) * co1 + sigf(iv1) * tanhf_f(gv1);
            float hn1 = sigf(ov1) * tanhf_f(cn1);

            outC[(size_t)r * PG4 + u] = cn0;
            outH[(size_t)r * PG4 + u] = hn0;
            outC[(size_t)(r + 8) * PG4 + u] = cn1;
            outH[(size_t)(r + 8) * PG4 + u] = hn1;
            if (outH16) {
                outH16[(size_t)r * PK + u] = __float2half_rn(hn0);
                outH16[(size_t)(r + 8) * PK + u] = __float2half_rn(hn1);
            }

            int pc = cbase + u, ph = pc + 128;
            float2 wrc = Wr2[pc], wrh = Wr2[ph];
            float2 wbc = Wb2[pc], wbh = Wb2[ph];
            s0a = fmaf(cn0, wrc.x, fmaf(hn0, wrh.x, s0a));
            s1a = fmaf(cn0, wrc.y, fmaf(hn0, wrh.y, s1a));
            s2a = fmaf(cn0, wbc.x, fmaf(hn0, wbh.x, s2a));
            s3a = fmaf(cn0, wbc.y, fmaf(hn0, wbh.y, s3a));
            s0b = fmaf(cn1, wrc.x, fmaf(hn1, wrh.x, s0b));
            s1b = fmaf(cn1, wrc.y, fmaf(hn1, wrh.y, s1b));
            s2b = fmaf(cn1, wbc.x, fmaf(hn1, wbh.x, s2b));
            s3b = fmaf(cn1, wbc.y, fmaf(hn1, wbh.y, s3b));
        }
#pragma unroll
        for (int o = 1; o <= 2; o <<= 1) {
            s0a += __shfl_xor_sync(0xffffffffu, s0a, o);
            s1a += __shfl_xor_sync(0xffffffffu, s1a, o);
            s2a += __shfl_xor_sync(0xffffffffu, s2a, o);
            s3a += __shfl_xor_sync(0xffffffffu, s3a, o);
            s0b += __shfl_xor_sync(0xffffffffu, s0b, o);
            s1b += __shfl_xor_sync(0xffffffffu, s1b, o);
            s2b += __shfl_xor_sync(0xffffffffu, s2b, o);
            s3b += __shfl_xor_sync(0xffffffffu, s3b, o);
        }
        if ((lane & 3) == 0) {
            red4(&g_logits[(size_t)r * 4], s0a, s1a, s2a, s3a);
            red4(&g_logits[(size_t)(r + 8) * 4], s0b, s1b, s2b, s3b);
        }
    }
}

// ---------------- mask exit/raise nodes: contrib <- old state ----------------
__global__ void ip_mask(const float* __restrict__ hc0, const float* __restrict__ hh0,
                        const float* __restrict__ hc1, const float* __restrict__ hh1,
                        const int* __restrict__ exi, const int* __restrict__ rai)
{
    int b = blockIdx.x;
    int node = blockIdx.y ? rai[b] : exi[b];
    int tid = threadIdx.x;  // 128
    size_t r = (size_t)b * PN + node;
    float* dst = g_contrib + r * PG4;
    size_t rb = r * PH;
    dst[tid]       = hc0[rb + tid];
    dst[128 + tid] = hh0[rb + tid];
    dst[256 + tid] = hc1[rb + tid];
    dst[384 + tid] = hh1[rb + tid];
}

// ---------------- recompute logits for masked rows ----------------
__global__ void ip_fixlog(const int* __restrict__ exi, const int* __restrict__ rai,
                          const float* __restrict__ Wr, const float* __restrict__ Wb)
{
    int b = blockIdx.x;
    int node = blockIdx.y ? rai[b] : exi[b];
    int lane = threadIdx.x;  // 32
    int row = (b << 11) + node;
    const float* crow = g_contrib + (size_t)row * PG4;

    float r0 = 0.f, r1 = 0.f, q0 = 0.f, q1 = 0.f;
#pragma unroll
    for (int t2 = 0; t2 < 4; t2++) {
        int cb = lane * 4 + t2 * 128;
        float4 v = *(const float4*)&crow[cb];
        float vv[4] = {v.x, v.y, v.z, v.w};
#pragma unroll
        for (int q = 0; q < 4; q++) {
            float w = vv[q];
            int c2 = (cb + q) * 2;
            r0 = fmaf(w, Wr[c2 + 0], r0);
            r1 = fmaf(w, Wr[c2 + 1], r1);
            q0 = fmaf(w, Wb[c2 + 0], q0);
            q1 = fmaf(w, Wb[c2 + 1], q1);
        }
    }
#pragma unroll
    for (int o = 16; o > 0; o >>= 1) {
        r0 += __shfl_xor_sync(0xffffffffu, r0, o);
        r1 += __shfl_xor_sync(0xffffffffu, r1, o);
        q0 += __shfl_xor_sync(0xffffffffu, q0, o);
        q1 += __shfl_xor_sync(0xffffffffu, q1, o);
    }
    if (lane == 0)
        ((float4*)g_logits)[row] = make_float4(r0, r1, q0, q1);
}

// ---------------- edge weights from logits + CSR fill (self-cleans logits) ---
__global__ __launch_bounds__(256) void ip_edges(
    const float* __restrict__ brs, const float* __restrict__ bbs,
    const float* __restrict__ ipin,
    const int* __restrict__ ti, const int* __restrict__ fi, const int* __restrict__ ri,
    const int* __restrict__ exi, const int* __restrict__ rai,
    const int* __restrict__ slim, const int* __restrict__ cstep, int cs_fallback)
{
    int row = blockIdx.x * 256 + threadIdx.x;
    int b = row >> 11, n = row & 2047;

    float4 L = ((const float4*)g_logits)[row];
    ((float4*)g_logits)[row] = make_float4(0.f, 0.f, 0.f, 0.f);  // self-clean

    int cs = cstep ? cstep[0] : cs_fallback;
    if (cs >= slim[b]) return;

    float lr = (L.x + brs[0]) - (L.y + brs[1]);
    float p_raise = sigf(lr);
    float p_no = 1.0f - p_raise;
    if (n == exi[b] || n == rai[b]) { p_raise = 0.0f; p_no = 1.0f; }
    float lb = (L.z + bbs[0]) - (L.w + bbs[1]);
    float pb0 = sigf(lb);
    float pb1 = 1.0f - pb0;

    float ipv = ipin[row];
    float wr_ = p_raise * ipv;
    float wt_ = p_no * pb0 * ipv;
    float wf_ = p_no * pb1 * ipv;

    int bb2 = b << 11;
    int tr = bb2 + ri[row], tt = bb2 + ti[row], tf = bb2 + fi[row];
    atomicAdd(&g_ipnew[tr], wr_);
    atomicAdd(&g_ipnew[tt], wt_);
    atomicAdd(&g_ipnew[tf], wf_);
    if (wr_ != 0.0f) {
        int s = atomicAdd(&g_cur[tr], 1);
        g_esrc[s] = row; g_ew[s] = wr_;
    }
    if (wt_ != 0.0f) {
        int s = atomicAdd(&g_cur[tt], 1);
        g_esrc[s] = row; g_ew[s] = wt_;
    }
    if (wf_ != 0.0f) {
        int s = atomicAdd(&g_cur[tf], 1);
        g_esrc[s] = row; g_ew[s] = wf_;
    }
}

// ---------------- gather + finalize ----------------
__global__ __launch_bounds__(128) void ip_gather(
    const float* __restrict__ hc0, const float* __restrict__ hh0,
    const float* __restrict__ hc1, const float* __restrict__ hh1,
    const float* __restrict__ ipold, const int* __restrict__ slim,
    const int* __restrict__ cstep, int cs_fallback, float* __restrict__ out)
{
    int row = blockIdx.x;
    int tid = threadIdx.x;  // 128
    int b = row >> 11;
    int cs = cstep ? cstep[0] : cs_fallback;
    bool nd = cs < slim[b];
    size_t ob = (size_t)row * 513;
    if (nd) {
        int s = g_off[row], e = g_cur[row];
        const float4* cb = (const float4*)g_contrib;
        float ax = 0.f, ay = 0.f, az = 0.f, aw = 0.f;
        for (int i = s; i < e; i++) {
            float w = g_ew[i];
            int src = g_esrc[i];
            float4 v = cb[(size_t)src * 128 + tid];
            ax = fmaf(w, v.x, ax); ay = fmaf(w, v.y, ay);
            az = fmaf(w, v.z, az); aw = fmaf(w, v.w, aw);
        }
        float ipn = g_ipnew[row];
        float inv = __fdividef(1.0f, ipn + 1e-7f);
        out[ob + 4 * tid + 0] = ax * inv;
        out[ob + 4 * tid + 1] = ay * inv;
        out[ob + 4 * tid + 2] = az * inv;
        out[ob + 4 * tid + 3] = aw * inv;
        if (tid == 0) out[ob + 512] = ipn;
    } else {
        size_t rb = (size_t)row * PH;
        out[ob + tid]       = hc0[rb + tid];
        out[ob + 128 + tid] = hh0[rb + tid];
        out[ob + 256 + tid] = hc1[rb + tid];
        out[ob + 384 + tid] = hh1[rb + tid];
        if (tid == 0) out[ob + 512] = ipold[row];
    }
}

// ---------------- host launcher ----------------
extern "C" void kernel_launch(void* const* d_in, const int* in_sizes, int n_in,
                              void* d_out, int out_size)
{
    const float* emb  = (const float*)d_in[0];
    const float* hc0  = (const float*)d_in[1];
    const float* hh0  = (const float*)d_in[2];
    const float* hc1  = (const float*)d_in[3];
    const float* hh1  = (const float*)d_in[4];
    const float* ip   = (const float*)d_in[5];
    const float* Wi0  = (const float*)d_in[6];
    const float* Wh0  = (const float*)d_in[7];
    const float* b0   = (const float*)d_in[8];
    const float* Wi1  = (const float*)d_in[9];
    const float* Wh1  = (const float*)d_in[10];
    const float* b1   = (const float*)d_in[11];
    const float* Wr   = (const float*)d_in[12];
    const float* br   = (const float*)d_in[13];
    const float* Wb   = (const float*)d_in[14];
    const float* bb   = (const float*)d_in[15];
    const int* ti     = (const int*)d_in[16];
    const int* fi     = (const int*)d_in[17];
    const int* ri     = (const int*)d_in[18];
    const int* exi    = (const int*)d_in[19];
    const int* rai    = (const int*)d_in[20];
    const int* slim   = (const int*)d_in[21];
    const int* cstep  = (n_in >= 23) ? (const int*)d_in[22] : nullptr;
    float* out = (float*)d_out;

    float *contrib, *bP0, *bP1;
    __half *A0, *A1, *WT0h, *WT1h;
    cudaGetSymbolAddress((void**)&contrib, g_contrib);
    cudaGetSymbolAddress((void**)&A0,      g_A0);
    cudaGetSymbolAddress((void**)&A1,      g_A1);
    cudaGetSymbolAddress((void**)&WT0h,    g_WT0h);
    cudaGetSymbolAddress((void**)&WT1h,    g_WT1h);
    cudaGetSymbolAddress((void**)&bP0,     g_bP0);
    cudaGetSymbolAddress((void**)&bP1,     g_bP1);

    cudaFuncSetAttribute(ip_lstm_mma,
                         cudaFuncAttributeMaxDynamicSharedMemorySize, SMEM_TOTAL_GEMM);

    // kernels 0-2, then gemm0 at kernel index 3 (ncu capture slot)
    ip_cvt16<<<dim3(PM * PH / 4 / 256, 3), 256>>>(emb, hh0, hh1);     // 0
    ip_permW<<<512, 256>>>(Wi0, Wh0, b0, WT0h, bP0);                  // 1
    ip_permW<<<512, 256>>>(Wi1, Wh1, b1, WT1h, bP1);                  // 2

    dim3 ggrid(4, PM / 128);
    // Layer 0 (kernel 3): A=g_A0, writes h0n16 into g_A1[:,0:128)
    ip_lstm_mma<<<ggrid, 256, SMEM_TOTAL_GEMM>>>(
        A0, hc0, WT0h, bP0, Wr, Wb, 0, contrib + 0, contrib + 128, A1);
    // Layer 1 (kernel 4): A=g_A1
    ip_lstm_mma<<<ggrid, 256, SMEM_TOTAL_GEMM>>>(
        A1, hc1, WT1h, bP1, Wr, Wb, 256, contrib + 256, contrib + 384, nullptr);

    ip_count<<<PM / 256, 256>>>(ti, fi, ri);

    ip_scan<<<PB, 512>>>();

    ip_mask<<<dim3(PB, 2), 128>>>(hc0, hh0, hc1, hh1, exi, rai);

    ip_fixlog<<<dim3(PB, 2), 32>>>(exi, rai, Wr, Wb);

    ip_edges<<<PM / 256, 256>>>(br, bb, ip, ti, fi, ri, exi, rai, slim, cstep, 5);

    ip_gather<<<PM, 128>>>(hc0, hh0, hc1, hh1, ip, slim, cstep, 5, out);
}

// round 13
// speedup vs baseline: 1.3127x; 1.0267x over previous
#include <cuda_runtime.h>
#include <cuda_fp16.h>
#include <math.h>
#include <stdint.h>

// Problem constants
#define PB 32
#define PN 2048
#define PH 128
#define PG4 512
#define PM (PB * PN)   // 65536 rows
#define PK 256         // combined K = [X | H]

// ---------------- device scratch (no allocations allowed) ----------------
__device__ float  g_contrib[(size_t)PM * PG4];  // [c0 | h0 | c1 | h1] per row (fp32)
__device__ __half g_A0[(size_t)PM * PK];        // layer0 A: [emb | hh0] half
__device__ __half g_A1[(size_t)PM * PK];        // layer1 A: [h0n | hh1] half
__device__ __half g_WT0h[PG4 * PK];             // layer0 weights [n][k] half
__device__ __half g_WT1h[PG4 * PK];             // layer1 weights half
__device__ float  g_bP0[PG4];
__device__ float  g_bP1[PG4];
__device__ float  g_logits[(size_t)PM * 4];     // per-row [r0, r1, b0, b1]
__device__ float  g_ipnew[PM];
__device__ int    g_cnt[PM];                    // zero-init at load; scan re-zeroes
__device__ int    g_off[PM];
__device__ int    g_cur[PM];
__device__ int    g_esrc[3 * PM];
__device__ float  g_ew[3 * PM];

// ---------------- helpers ----------------
__device__ __forceinline__ uint32_t smem_u32(const void* p) {
    uint32_t a;
    asm("{ .reg .u64 t; cvta.to.shared.u64 t, %1; cvt.u32.u64 %0, t; }" : "=r"(a) : "l"(p));
    return a;
}
__device__ __forceinline__ void mma16(float* d, const uint32_t* a, const uint32_t* b) {
    asm volatile(
        "mma.sync.aligned.m16n8k16.row.col.f32.f16.f16.f32 "
        "{%0,%1,%2,%3}, {%4,%5,%6,%7}, {%8,%9}, {%0,%1,%2,%3};"
        : "+f"(d[0]), "+f"(d[1]), "+f"(d[2]), "+f"(d[3])
        : "r"(a[0]), "r"(a[1]), "r"(a[2]), "r"(a[3]), "r"(b[0]), "r"(b[1]));
}
__device__ __forceinline__ void red4(float* p, float a, float b, float c, float d) {
    asm volatile("red.global.add.v4.f32 [%0], {%1,%2,%3,%4};"
                 :: "l"(p), "f"(a), "f"(b), "f"(c), "f"(d) : "memory");
}
#define CP_ASYNC16(s, g) asm volatile("cp.async.cg.shared.global [%0], [%1], 16;" :: "r"(s), "l"(g))
#define CP_COMMIT() asm volatile("cp.async.commit_group;" ::: "memory")
#define CP_WAIT0() asm volatile("cp.async.wait_group 0;" ::: "memory")
#define CP_WAIT1() asm volatile("cp.async.wait_group 1;" ::: "memory")

__device__ __forceinline__ float sigf(float x) {
    return __fdividef(1.0f, 1.0f + __expf(-x));
}
__device__ __forceinline__ float tanhf_f(float x) {
    float xc = fminf(fmaxf(x, -15.0f), 15.0f);
    float e = __expf(2.0f * xc);
    return __fdividef(e - 1.0f, e + 1.0f);
}

// ---------------- prelude: pack A operands as half ----------------
__global__ void ip_cvt16(const float* __restrict__ emb, const float* __restrict__ hh0,
                         const float* __restrict__ hh1)
{
    int i = blockIdx.x * 256 + threadIdx.x;     // [0, PM*PH/4)
    int s = blockIdx.y;
    const float4* src = (const float4*)(s == 0 ? emb : (s == 1 ? hh0 : hh1));
    float4 v = src[i];
    int r = i >> 5, c4 = i & 31;
    __half2 h0 = __floats2half2_rn(v.x, v.y);
    __half2 h1 = __floats2half2_rn(v.z, v.w);
    __half2* dst = (__half2*)(s == 2 ? g_A1 : g_A0);
    int off = r * 128 + (s == 0 ? 0 : 64) + c4 * 2;
    dst[off] = h0;
    dst[off + 1] = h1;
}

// ---------------- weight prep (half) ----------------
__device__ __forceinline__ int perm_oc(int n) {
    int blk = n >> 4, w = n & 15;
    int ghi = w >> 3, pos = (w & 7) >> 1, glo = w & 1;
    int u = blk * 4 + pos;
    int g = ghi * 2 + glo;
    return g * 128 + u;
}
__global__ void ip_permW(const float* __restrict__ Wi, const float* __restrict__ Wh,
                         const float* __restrict__ bsrc,
                         __half* __restrict__ WT, float* __restrict__ bdst)
{
    int t = blockIdx.x * 256 + threadIdx.x;
    int n = t >> 8;
    int k = t & 255;
    int oc = perm_oc(n);
    float w = (k < 128) ? Wi[k * PG4 + oc] : Wh[(k - 128) * PG4 + oc];
    WT[t] = __float2half_rn(w);
    if (k == 0) bdst[n] = bsrc[oc];
}

// ---------------- CSR: count ----------------
__global__ void ip_count(const int* __restrict__ ti, const int* __restrict__ fi,
                         const int* __restrict__ ri)
{
    int s = blockIdx.x * 256 + threadIdx.x;
    int bb = (s >> 11) << 11;
    atomicAdd(&g_cnt[bb + ri[s]], 1);
    atomicAdd(&g_cnt[bb + ti[s]], 1);
    atomicAdd(&g_cnt[bb + fi[s]], 1);
}

// ---------------- CSR scan; re-zeroes g_cnt; zeroes ipnew ------------------
__global__ __launch_bounds__(512) void ip_scan()
{
    __shared__ int part[512];
    int b = blockIdx.x;
    int t = threadIdx.x;
    int base = b << 11;

    int c0 = g_cnt[base + 4 * t + 0];
    int c1 = g_cnt[base + 4 * t + 1];
    int c2 = g_cnt[base + 4 * t + 2];
    int c3 = g_cnt[base + 4 * t + 3];
    g_cnt[base + 4 * t + 0] = 0;
    g_cnt[base + 4 * t + 1] = 0;
    g_cnt[base + 4 * t + 2] = 0;
    g_cnt[base + 4 * t + 3] = 0;
    int l0 = c0, l1 = l0 + c1, l2 = l1 + c2, l3 = l2 + c3;
    part[t] = l3;
    __syncthreads();
    for (int o = 1; o < 512; o <<= 1) {
        int v = (t >= o) ? part[t - o] : 0;
        __syncthreads();
        part[t] += v;
        __syncthreads();
    }
    int ex = (t == 0) ? 0 : part[t - 1];
    int gb = b * 6144 + ex;
    g_off[base + 4 * t + 0] = gb;
    g_off[base + 4 * t + 1] = gb + l0;
    g_off[base + 4 * t + 2] = gb + l1;
    g_off[base + 4 * t + 3] = gb + l2;
    g_cur[base + 4 * t + 0] = gb;
    g_cur[base + 4 * t + 1] = gb + l0;
    g_cur[base + 4 * t + 2] = gb + l1;
    g_cur[base + 4 * t + 3] = gb + l2;
    g_ipnew[base + 4 * t + 0] = 0.0f;
    g_ipnew[base + 4 * t + 1] = 0.0f;
    g_ipnew[base + 4 * t + 2] = 0.0f;
    g_ipnew[base + 4 * t + 3] = 0.0f;
}

// ---------------- fp16 mma.sync GEMM + fused LSTM + logit epilogue ----------
// CTA 128x128, 8 warps (4M x 2N). K=256 in 4 chunks of 64 halves (128B rows,
// padded to 144B). 3-stage all-cp.async pipeline; 4 k16-steps per barrier-free region.
#define A_STRIDE 36                               // words per row (144 B)
#define HALF_STAGE (128 * A_STRIDE * 4)           // 18432
#define STAGE_BYTES (2 * HALF_STAGE)              // 36864
#define SMEM_TOTAL_GEMM (3 * STAGE_BYTES)         // 110592

__global__ __launch_bounds__(256, 2) void ip_lstm_mma(
    const __half* __restrict__ Ah,
    const float* __restrict__ Cold,
    const __half* __restrict__ WT, const float* __restrict__ bP,
    const float* __restrict__ Wr, const float* __restrict__ Wb, int cbase,
    float* __restrict__ outC, float* __restrict__ outH,
    __half* __restrict__ outH16)
{
    extern __shared__ char smem[];

    int tid = threadIdx.x;
    int wid = tid >> 5, lane = tid & 31;
    int wm = wid & 3, wn = wid >> 2;
    int row0 = blockIdx.y * 128;
    int col0 = blockIdx.x * 128;

    float acc[2][8][4];
#pragma unroll
    for (int mt = 0; mt < 2; mt++)
#pragma unroll
        for (int nt = 0; nt < 8; nt++)
#pragma unroll
            for (int q = 0; q < 4; q++) acc[mt][nt][q] = 0.0f;

    float bI[4], bF[4], bG[4], bO[4];
#pragma unroll
    for (int p = 0; p < 4; p++) {
        int c0 = col0 + wn * 64 + p * 16 + (lane & 3) * 2;
        bI[p] = bP[c0];     bF[p] = bP[c0 + 1];
        bG[p] = bP[c0 + 8]; bO[p] = bP[c0 + 9];
    }

    // per chunk: A tile 128 rows x 128B = 1024 x16B units; same for B
    auto prefetch = [&](int c) {
        int kh = c * 64;                          // k offset in halves
        char* As = smem + (c % 3) * STAGE_BYTES;
        char* Bs = As + HALF_STAGE;
#pragma unroll
        for (int j = 0; j < 4; j++) {
            int fid = j * 256 + tid;              // [0,1024)
            int r = fid >> 3, q = fid & 7;
            CP_ASYNC16(smem_u32(As + r * 144 + q * 16),
                       Ah + (size_t)(row0 + r) * PK + kh + q * 8);
            CP_ASYNC16(smem_u32(Bs + r * 144 + q * 16),
                       WT + (size_t)(col0 + r) * PK + kh + q * 8);
        }
    };

    prefetch(0); CP_COMMIT();
    prefetch(1); CP_COMMIT();
    CP_WAIT1();
    __syncthreads();

    int a_base = (wm * 32 + (lane >> 2)) * A_STRIDE;
    int b_base = (wn * 64 + (lane >> 2)) * A_STRIDE;
    int kc = lane & 3;

#pragma unroll 1
    for (int ch = 0; ch < 4; ch++) {
        uint32_t* Abuf = (uint32_t*)(smem + (ch % 3) * STAGE_BYTES);
        uint32_t* Bbuf = (uint32_t*)(smem + (ch % 3) * STAGE_BYTES + HALF_STAGE);
#pragma unroll
        for (int ks = 0; ks < 4; ks++) {          // 4 x k16 per 64-half chunk
            int kk = ks * 8 + kc;
            uint32_t a[2][4];
#pragma unroll
            for (int mt = 0; mt < 2; mt++) {
                int rb = a_base + mt * 16 * A_STRIDE;
                a[mt][0] = Abuf[rb + kk];
                a[mt][1] = Abuf[rb + 8 * A_STRIDE + kk];
                a[mt][2] = Abuf[rb + kk + 4];
                a[mt][3] = Abuf[rb + 8 * A_STRIDE + kk + 4];
            }
            uint32_t b[8][2];
#pragma unroll
            for (int nt = 0; nt < 8; nt++) {
                int nb = b_base + nt * 8 * A_STRIDE;
                b[nt][0] = Bbuf[nb + kk];
                b[nt][1] = Bbuf[nb + kk + 4];
            }
#pragma unroll
            for (int mt = 0; mt < 2; mt++)
#pragma unroll
                for (int nt = 0; nt < 8; nt++)
                    mma16(acc[mt][nt], a[mt], b[nt]);
        }

        if (ch < 3) {
            if (ch < 2) {
                prefetch(ch + 2);
                CP_COMMIT();
                CP_WAIT1();          // ch+1 resident
            } else {
                CP_WAIT0();          // last chunk resident
            }
            __syncthreads();
        }
    }

    // ---- fused LSTM epilogue + per-row logit partials ----
    const float2* Wr2 = (const float2*)Wr;
    const float2* Wb2 = (const float2*)Wb;
#pragma unroll
    for (int mt = 0; mt < 2; mt++) {
        int r = row0 + wm * 32 + mt * 16 + (lane >> 2);
        float s0a = 0.f, s1a = 0.f, s2a = 0.f, s3a = 0.f;
        float s0b = 0.f, s1b = 0.f, s2b = 0.f, s3b = 0.f;
#pragma unroll
        for (int p = 0; p < 4; p++) {
            int u = (col0 >> 2) + wn * 16 + p * 4 + (lane & 3);
            float co0 = Cold[(size_t)r * PH + u];
            float co1 = Cold[(size_t)(r + 8) * PH + u];
            float iv = acc[mt][2 * p][0] + bI[p];
            float fv = acc[mt][2 * p][1] + bF[p];
            float gv = acc[mt][2 * p + 1][0] + bG[p];
            float ov = acc[mt][2 * p + 1][1] + bO[p];
            float cn0 = sigf(fv) * co0 + sigf(iv) * tanhf_f(gv);
            float hn0 = sigf(ov) * tanhf_f(cn0);
            float iv1 = acc[mt][2 * p][2] + bI[p];
            float fv1 = acc[mt][2 * p][3] + bF[p];
            float gv1 = acc[mt][2 * p + 1][2] + bG[p];
            float ov1 = acc[mt][2 * p + 1][3] + bO[p];
            float cn1 = sigf(fv1) * co1 + sigf(iv1) * tanhf_f(gv1);
            float hn1 = sigf(ov1) * tanhf_f(cn1);

            outC[(size_t)r * PG4 + u] = cn0;
            outH[(size_t)r * PG4 + u] = hn0;
            outC[(size_t)(r + 8) * PG4 + u] = cn1;
            outH[(size_t)(r + 8) * PG4 + u] = hn1;
            if (outH16) {
                outH16[(size_t)r * PK + u] = __float2half_rn(hn0);
                outH16[(size_t)(r + 8) * PK + u] = __float2half_rn(hn1);
            }

            int pc = cbase + u, ph = pc + 128;
            float2 wrc = Wr2[pc], wrh = Wr2[ph];
            float2 wbc = Wb2[pc], wbh = Wb2[ph];
            s0a = fmaf(cn0, wrc.x, fmaf(hn0, wrh.x, s0a));
            s1a = fmaf(cn0, wrc.y, fmaf(hn0, wrh.y, s1a));
            s2a = fmaf(cn0, wbc.x, fmaf(hn0, wbh.x, s2a));
            s3a = fmaf(cn0, wbc.y, fmaf(hn0, wbh.y, s3a));
            s0b = fmaf(cn1, wrc.x, fmaf(hn1, wrh.x, s0b));
            s1b = fmaf(cn1, wrc.y, fmaf(hn1, wrh.y, s1b));
            s2b = fmaf(cn1, wbc.x, fmaf(hn1, wbh.x, s2b));
            s3b = fmaf(cn1, wbc.y, fmaf(hn1, wbh.y, s3b));
        }
#pragma unroll
        for (int o = 1; o <= 2; o <<= 1) {
            s0a += __shfl_xor_sync(0xffffffffu, s0a, o);
            s1a += __shfl_xor_sync(0xffffffffu, s1a, o);
            s2a += __shfl_xor_sync(0xffffffffu, s2a, o);
            s3a += __shfl_xor_sync(0xffffffffu, s3a, o);
            s0b += __shfl_xor_sync(0xffffffffu, s0b, o);
            s1b += __shfl_xor_sync(0xffffffffu, s1b, o);
            s2b += __shfl_xor_sync(0xffffffffu, s2b, o);
            s3b += __shfl_xor_sync(0xffffffffu, s3b, o);
        }
        if ((lane & 3) == 0) {
            red4(&g_logits[(size_t)r * 4], s0a, s1a, s2a, s3a);
            red4(&g_logits[(size_t)(r + 8) * 4], s0b, s1b, s2b, s3b);
        }
    }
}

// ---------------- mask exit/raise nodes ----------------
__global__ void ip_mask(const float* __restrict__ hc0, const float* __restrict__ hh0,
                        const float* __restrict__ hc1, const float* __restrict__ hh1,
                        const int* __restrict__ exi, const int* __restrict__ rai)
{
    int b = blockIdx.x;
    int node = blockIdx.y ? rai[b] : exi[b];
    int tid = threadIdx.x;  // 128
    size_t r = (size_t)b * PN + node;
    float* dst = g_contrib + r * PG4;
    size_t rb = r * PH;
    dst[tid]       = hc0[rb + tid];
    dst[128 + tid] = hh0[rb + tid];
    dst[256 + tid] = hc1[rb + tid];
    dst[384 + tid] = hh1[rb + tid];
}

// ---------------- recompute logits for masked rows ----------------
__global__ void ip_fixlog(const int* __restrict__ exi, const int* __restrict__ rai,
                          const float* __restrict__ Wr, const float* __restrict__ Wb)
{
    int b = blockIdx.x;
    int node = blockIdx.y ? rai[b] : exi[b];
    int lane = threadIdx.x;  // 32
    int row = (b << 11) + node;
    const float* crow = g_contrib + (size_t)row * PG4;

    float r0 = 0.f, r1 = 0.f, q0 = 0.f, q1 = 0.f;
#pragma unroll
    for (int t2 = 0; t2 < 4; t2++) {
        int cb = lane * 4 + t2 * 128;
        float4 v = *(const float4*)&crow[cb];
        float vv[4] = {v.x, v.y, v.z, v.w};
#pragma unroll
        for (int q = 0; q < 4; q++) {
            float w = vv[q];
            int c2 = (cb + q) * 2;
            r0 = fmaf(w, Wr[c2 + 0], r0);
            r1 = fmaf(w, Wr[c2 + 1], r1);
            q0 = fmaf(w, Wb[c2 + 0], q0);
            q1 = fmaf(w, Wb[c2 + 1], q1);
        }
    }
#pragma unroll
    for (int o = 16; o > 0; o >>= 1) {
        r0 += __shfl_xor_sync(0xffffffffu, r0, o);
        r1 += __shfl_xor_sync(0xffffffffu, r1, o);
        q0 += __shfl_xor_sync(0xffffffffu, q0, o);
        q1 += __shfl_xor_sync(0xffffffffu, q1, o);
    }
    if (lane == 0)
        ((float4*)g_logits)[row] = make_float4(r0, r1, q0, q1);
}

// ---------------- edge weights from logits + CSR fill ----------------
__global__ __launch_bounds__(256) void ip_edges(
    const float* __restrict__ brs, const float* __restrict__ bbs,
    const float* __restrict__ ipin,
    const int* __restrict__ ti, const int* __restrict__ fi, const int* __restrict__ ri,
    const int* __restrict__ exi, const int* __restrict__ rai,
    const int* __restrict__ slim, const int* __restrict__ cstep, int cs_fallback)
{
    int row = blockIdx.x * 256 + threadIdx.x;
    int b = row >> 11, n = row & 2047;

    float4 L = ((const float4*)g_logits)[row];
    ((float4*)g_logits)[row] = make_float4(0.f, 0.f, 0.f, 0.f);  // self-clean

    int cs = cstep ? cstep[0] : cs_fallback;
    if (cs >= slim[b]) return;

    float lr = (L.x + brs[0]) - (L.y + brs[1]);
    float p_raise = sigf(lr);
    float p_no = 1.0f - p_raise;
    if (n == exi[b] || n == rai[b]) { p_raise = 0.0f; p_no = 1.0f; }
    float lb = (L.z + bbs[0]) - (L.w + bbs[1]);
    float pb0 = sigf(lb);
    float pb1 = 1.0f - pb0;

    float ipv = ipin[row];
    float wr_ = p_raise * ipv;
    float wt_ = p_no * pb0 * ipv;
    float wf_ = p_no * pb1 * ipv;

    int bb2 = b << 11;
    int tr = bb2 + ri[row], tt = bb2 + ti[row], tf = bb2 + fi[row];
    atomicAdd(&g_ipnew[tr], wr_);
    atomicAdd(&g_ipnew[tt], wt_);
    atomicAdd(&g_ipnew[tf], wf_);
    if (wr_ != 0.0f) {
        int s = atomicAdd(&g_cur[tr], 1);
        g_esrc[s] = row; g_ew[s] = wr_;
    }
    if (wt_ != 0.0f) {
        int s = atomicAdd(&g_cur[tt], 1);
        g_esrc[s] = row; g_ew[s] = wt_;
    }
    if (wf_ != 0.0f) {
        int s = atomicAdd(&g_cur[tf], 1);
        g_esrc[s] = row; g_ew[s] = wf_;
    }
}

// ---------------- gather + finalize ----------------
__global__ __launch_bounds__(128) void ip_gather(
    const float* __restrict__ hc0, const float* __restrict__ hh0,
    const float* __restrict__ hc1, const float* __restrict__ hh1,
    const float* __restrict__ ipold, const int* __restrict__ slim,
    const int* __restrict__ cstep, int cs_fallback, float* __restrict__ out)
{
    int row = blockIdx.x;
    int tid = threadIdx.x;  // 128
    int b = row >> 11;
    int cs = cstep ? cstep[0] : cs_fallback;
    bool nd = cs < slim[b];
    size_t ob = (size_t)row * 513;
    if (nd) {
        int s = g_off[row], e = g_cur[row];
        const float4* cb = (const float4*)g_contrib;
        float ax = 0.f, ay = 0.f, az = 0.f, aw = 0.f;
        for (int i = s; i < e; i++) {
            float w = g_ew[i];
            int src = g_esrc[i];
            float4 v = cb[(size_t)src * 128 + tid];
            ax = fmaf(w, v.x, ax); ay = fmaf(w, v.y, ay);
            az = fmaf(w, v.z, az); aw = fmaf(w, v.w, aw);
        }
        float ipn = g_ipnew[row];
        float inv = __fdividef(1.0f, ipn + 1e-7f);
        out[ob + 4 * tid + 0] = ax * inv;
        out[ob + 4 * tid + 1] = ay * inv;
        out[ob + 4 * tid + 2] = az * inv;
        out[ob + 4 * tid + 3] = aw * inv;
        if (tid == 0) out[ob + 512] = ipn;
    } else {
        size_t rb = (size_t)row * PH;
        out[ob + tid]       = hc0[rb + tid];
        out[ob + 128 + tid] = hh0[rb + tid];
        out[ob + 256 + tid] = hc1[rb + tid];
        out[ob + 384 + tid] = hh1[rb + tid];
        if (tid == 0) out[ob + 512] = ipold[row];
    }
}

// ---------------- host launcher ----------------
extern "C" void kernel_launch(void* const* d_in, const int* in_sizes, int n_in,
                              void* d_out, int out_size)
{
    const float* emb  = (const float*)d_in[0];
    const float* hc0  = (const float*)d_in[1];
    const float* hh0  = (const float*)d_in[2];
    const float* hc1  = (const float*)d_in[3];
    const float* hh1  = (const float*)d_in[4];
    const float* ip   = (const float*)d_in[5];
    const float* Wi0  = (const float*)d_in[6];
    const float* Wh0  = (const float*)d_in[7];
    const float* b0   = (const float*)d_in[8];
    const float* Wi1  = (const float*)d_in[9];
    const float* Wh1  = (const float*)d_in[10];
    const float* b1   = (const float*)d_in[11];
    const float* Wr   = (const float*)d_in[12];
    const float* br   = (const float*)d_in[13];
    const float* Wb   = (const float*)d_in[14];
    const float* bb   = (const float*)d_in[15];
    const int* ti     = (const int*)d_in[16];
    const int* fi     = (const int*)d_in[17];
    const int* ri     = (const int*)d_in[18];
    const int* exi    = (const int*)d_in[19];
    const int* rai    = (const int*)d_in[20];
    const int* slim   = (const int*)d_in[21];
    const int* cstep  = (n_in >= 23) ? (const int*)d_in[22] : nullptr;
    float* out = (float*)d_out;

    float *contrib, *bP0, *bP1;
    __half *A0, *A1, *WT0h, *WT1h;
    cudaGetSymbolAddress((void**)&contrib, g_contrib);
    cudaGetSymbolAddress((void**)&A0,      g_A0);
    cudaGetSymbolAddress((void**)&A1,      g_A1);
    cudaGetSymbolAddress((void**)&WT0h,    g_WT0h);
    cudaGetSymbolAddress((void**)&WT1h,    g_WT1h);
    cudaGetSymbolAddress((void**)&bP0,     g_bP0);
    cudaGetSymbolAddress((void**)&bP1,     g_bP1);

    cudaFuncSetAttribute(ip_lstm_mma,
                         cudaFuncAttributeMaxDynamicSharedMemorySize, SMEM_TOTAL_GEMM);

    // kernels 0-2, then gemm0 at kernel index 3 (ncu capture slot)
    ip_cvt16<<<dim3(PM * PH / 4 / 256, 3), 256>>>(emb, hh0, hh1);     // 0
    ip_permW<<<512, 256>>>(Wi0, Wh0, b0, WT0h, bP0);                  // 1
    ip_permW<<<512, 256>>>(Wi1, Wh1, b1, WT1h, bP1);                  // 2

    dim3 ggrid(4, PM / 128);
    // Layer 0 (kernel 3): A=g_A0, writes h0n16 into g_A1[:,0:128)
    ip_lstm_mma<<<ggrid, 256, SMEM_TOTAL_GEMM>>>(
        A0, hc0, WT0h, bP0, Wr, Wb, 0, contrib + 0, contrib + 128, A1);
    // Layer 1 (kernel 4): A=g_A1
    ip_lstm_mma<<<ggrid, 256, SMEM_TOTAL_GEMM>>>(
        A1, hc1, WT1h, bP1, Wr, Wb, 256, contrib + 256, contrib + 384, nullptr);

    ip_count<<<PM / 256, 256>>>(ti, fi, ri);

    ip_scan<<<PB, 512>>>();

    ip_mask<<<dim3(PB, 2), 128>>>(hc0, hh0, hc1, hh1, exi, rai);

    ip_fixlog<<<dim3(PB, 2), 32>>>(exi, rai, Wr, Wb);

    ip_edges<<<PM / 256, 256>>>(br, bb, ip, ti, fi, ri, exi, rai, slim, cstep, 5);

    ip_gather<<<PM, 128>>>(hc0, hh0, hc1, hh1, ip, slim, cstep, 5, out);
}

// round 14
// speedup vs baseline: 1.3783x; 1.0499x over previous
#include <cuda_runtime.h>
#include <cuda_fp16.h>
#include <math.h>
#include <stdint.h>

// Problem constants
#define PB 32
#define PN 2048
#define PH 128
#define PG4 512
#define PM (PB * PN)   // 65536 rows
#define PK 256         // combined K = [X | H]

// ---------------- device scratch (no allocations allowed) ----------------
__device__ __half g_contrib[(size_t)PM * PG4];  // [c0 | h0 | c1 | h1] per row (fp16)
__device__ __half g_A0[(size_t)PM * PK];        // layer0 A: [emb | hh0] half
__device__ __half g_H1h[(size_t)PM * PH];       // hh1 half (layer1 A high-K source)
__device__ __half g_WT0h[PG4 * PK];             // layer0 weights [n][k] half
__device__ __half g_WT1h[PG4 * PK];             // layer1 weights half
__device__ float  g_bP0[PG4];
__device__ float  g_bP1[PG4];
__device__ float  g_logits[(size_t)PM * 4];     // per-row [r0, r1, b0, b1]
__device__ float  g_ipnew[PM];
__device__ int    g_cnt[PM];                    // zero-init at load; scan re-zeroes
__device__ int    g_off[PM];
__device__ int    g_cur[PM];
__device__ int    g_esrc[3 * PM];
__device__ float  g_ew[3 * PM];

// ---------------- helpers ----------------
__device__ __forceinline__ uint32_t smem_u32(const void* p) {
    uint32_t a;
    asm("{ .reg .u64 t; cvta.to.shared.u64 t, %1; cvt.u32.u64 %0, t; }" : "=r"(a) : "l"(p));
    return a;
}
__device__ __forceinline__ void mma16(float* d, const uint32_t* a, const uint32_t* b) {
    asm volatile(
        "mma.sync.aligned.m16n8k16.row.col.f32.f16.f16.f32 "
        "{%0,%1,%2,%3}, {%4,%5,%6,%7}, {%8,%9}, {%0,%1,%2,%3};"
        : "+f"(d[0]), "+f"(d[1]), "+f"(d[2]), "+f"(d[3])
        : "r"(a[0]), "r"(a[1]), "r"(a[2]), "r"(a[3]), "r"(b[0]), "r"(b[1]));
}
__device__ __forceinline__ void red4(float* p, float a, float b, float c, float d) {
    asm volatile("red.global.add.v4.f32 [%0], {%1,%2,%3,%4};"
                 :: "l"(p), "f"(a), "f"(b), "f"(c), "f"(d) : "memory");
}
#define CP_ASYNC16(s, g) asm volatile("cp.async.cg.shared.global [%0], [%1], 16;" :: "r"(s), "l"(g))
#define CP_COMMIT() asm volatile("cp.async.commit_group;" ::: "memory")
#define CP_WAIT0() asm volatile("cp.async.wait_group 0;" ::: "memory")
#define CP_WAIT1() asm volatile("cp.async.wait_group 1;" ::: "memory")

__device__ __forceinline__ float sigf(float x) {
    return __fdividef(1.0f, 1.0f + __expf(-x));
}
__device__ __forceinline__ float tanhf_f(float x) {
    float xc = fminf(fmaxf(x, -15.0f), 15.0f);
    float e = __expf(2.0f * xc);
    return __fdividef(e - 1.0f, e + 1.0f);
}

// ---------------- prelude: pack A operands as half ----------------
// section 0: emb -> g_A0[:,0:128); 1: hh0 -> g_A0[:,128:256); 2: hh1 -> g_H1h (stride 128)
__global__ void ip_cvt16(const float* __restrict__ emb, const float* __restrict__ hh0,
                         const float* __restrict__ hh1)
{
    int i = blockIdx.x * 256 + threadIdx.x;     // [0, PM*PH/4)
    int s = blockIdx.y;
    const float4* src = (const float4*)(s == 0 ? emb : (s == 1 ? hh0 : hh1));
    float4 v = src[i];
    int r = i >> 5, c4 = i & 31;
    __half2 h0 = __floats2half2_rn(v.x, v.y);
    __half2 h1 = __floats2half2_rn(v.z, v.w);
    if (s == 2) {
        __half2* dst = (__half2*)g_H1h;
        int off = r * 64 + c4 * 2;
        dst[off] = h0; dst[off + 1] = h1;
    } else {
        __half2* dst = (__half2*)g_A0;
        int off = r * 128 + (s == 0 ? 0 : 64) + c4 * 2;
        dst[off] = h0; dst[off + 1] = h1;
    }
}

// ---------------- weight prep (half) ----------------
__device__ __forceinline__ int perm_oc(int n) {
    int blk = n >> 4, w = n & 15;
    int ghi = w >> 3, pos = (w & 7) >> 1, glo = w & 1;
    int u = blk * 4 + pos;
    int g = ghi * 2 + glo;
    return g * 128 + u;
}
__global__ void ip_permW(const float* __restrict__ Wi, const float* __restrict__ Wh,
                         const float* __restrict__ bsrc,
                         __half* __restrict__ WT, float* __restrict__ bdst)
{
    int t = blockIdx.x * 256 + threadIdx.x;
    int n = t >> 8;
    int k = t & 255;
    int oc = perm_oc(n);
    float w = (k < 128) ? Wi[k * PG4 + oc] : Wh[(k - 128) * PG4 + oc];
    WT[t] = __float2half_rn(w);
    if (k == 0) bdst[n] = bsrc[oc];
}

// ---------------- CSR: count ----------------
__global__ void ip_count(const int* __restrict__ ti, const int* __restrict__ fi,
                         const int* __restrict__ ri)
{
    int s = blockIdx.x * 256 + threadIdx.x;
    int bb = (s >> 11) << 11;
    atomicAdd(&g_cnt[bb + ri[s]], 1);
    atomicAdd(&g_cnt[bb + ti[s]], 1);
    atomicAdd(&g_cnt[bb + fi[s]], 1);
}

// ---------------- CSR scan; re-zeroes g_cnt; zeroes ipnew ------------------
__global__ __launch_bounds__(512) void ip_scan()
{
    __shared__ int part[512];
    int b = blockIdx.x;
    int t = threadIdx.x;
    int base = b << 11;

    int c0 = g_cnt[base + 4 * t + 0];
    int c1 = g_cnt[base + 4 * t + 1];
    int c2 = g_cnt[base + 4 * t + 2];
    int c3 = g_cnt[base + 4 * t + 3];
    g_cnt[base + 4 * t + 0] = 0;
    g_cnt[base + 4 * t + 1] = 0;
    g_cnt[base + 4 * t + 2] = 0;
    g_cnt[base + 4 * t + 3] = 0;
    int l0 = c0, l1 = l0 + c1, l2 = l1 + c2, l3 = l2 + c3;
    part[t] = l3;
    __syncthreads();
    for (int o = 1; o < 512; o <<= 1) {
        int v = (t >= o) ? part[t - o] : 0;
        __syncthreads();
        part[t] += v;
        __syncthreads();
    }
    int ex = (t == 0) ? 0 : part[t - 1];
    int gb = b * 6144 + ex;
    g_off[base + 4 * t + 0] = gb;
    g_off[base + 4 * t + 1] = gb + l0;
    g_off[base + 4 * t + 2] = gb + l1;
    g_off[base + 4 * t + 3] = gb + l2;
    g_cur[base + 4 * t + 0] = gb;
    g_cur[base + 4 * t + 1] = gb + l0;
    g_cur[base + 4 * t + 2] = gb + l1;
    g_cur[base + 4 * t + 3] = gb + l2;
    g_ipnew[base + 4 * t + 0] = 0.0f;
    g_ipnew[base + 4 * t + 1] = 0.0f;
    g_ipnew[base + 4 * t + 2] = 0.0f;
    g_ipnew[base + 4 * t + 3] = 0.0f;
}

// ---------------- fp16 mma.sync GEMM + fused LSTM + logit epilogue ----------
// CTA 128x128, 8 warps (4M x 2N). K=256 in 4 chunks of 64 halves (128B rows,
// padded to 144B). 3-stage all-cp.async pipeline. A split: chunks 0-1 from
// (A0p, as0), chunks 2-3 from (A1p, as1). Outputs written as half into contrib.
#define A_STRIDE 36                               // words per row (144 B)
#define HALF_STAGE (128 * A_STRIDE * 4)           // 18432
#define STAGE_BYTES (2 * HALF_STAGE)              // 36864
#define SMEM_TOTAL_GEMM (3 * STAGE_BYTES)         // 110592

__global__ __launch_bounds__(256, 2) void ip_lstm_mma(
    const __half* __restrict__ A0p, int as0,
    const __half* __restrict__ A1p, int as1,
    const float* __restrict__ Cold,
    const __half* __restrict__ WT, const float* __restrict__ bP,
    const float* __restrict__ Wr, const float* __restrict__ Wb, int cbase,
    __half* __restrict__ outC, __half* __restrict__ outH)
{
    extern __shared__ char smem[];

    int tid = threadIdx.x;
    int wid = tid >> 5, lane = tid & 31;
    int wm = wid & 3, wn = wid >> 2;
    int row0 = blockIdx.y * 128;
    int col0 = blockIdx.x * 128;

    float acc[2][8][4];
#pragma unroll
    for (int mt = 0; mt < 2; mt++)
#pragma unroll
        for (int nt = 0; nt < 8; nt++)
#pragma unroll
            for (int q = 0; q < 4; q++) acc[mt][nt][q] = 0.0f;

    float bI[4], bF[4], bG[4], bO[4];
#pragma unroll
    for (int p = 0; p < 4; p++) {
        int c0 = col0 + wn * 64 + p * 16 + (lane & 3) * 2;
        bI[p] = bP[c0];     bF[p] = bP[c0 + 1];
        bG[p] = bP[c0 + 8]; bO[p] = bP[c0 + 9];
    }

    auto prefetch = [&](int c) {
        const __half* Asrc;
        int astr, kh;
        if (c < 2) { Asrc = A0p; astr = as0; kh = c * 64; }
        else       { Asrc = A1p; astr = as1; kh = (c - 2) * 64; }
        int kb = c * 64;
        char* As = smem + (c % 3) * STAGE_BYTES;
        char* Bs = As + HALF_STAGE;
#pragma unroll
        for (int j = 0; j < 4; j++) {
            int fid = j * 256 + tid;              // [0,1024)
            int r = fid >> 3, q = fid & 7;
            CP_ASYNC16(smem_u32(As + r * 144 + q * 16),
                       Asrc + (size_t)(row0 + r) * astr + kh + q * 8);
            CP_ASYNC16(smem_u32(Bs + r * 144 + q * 16),
                       WT + (size_t)(col0 + r) * PK + kb + q * 8);
        }
    };

    prefetch(0); CP_COMMIT();
    prefetch(1); CP_COMMIT();
    CP_WAIT1();
    __syncthreads();

    int a_base = (wm * 32 + (lane >> 2)) * A_STRIDE;
    int b_base = (wn * 64 + (lane >> 2)) * A_STRIDE;
    int kc = lane & 3;

#pragma unroll 1
    for (int ch = 0; ch < 4; ch++) {
        uint32_t* Abuf = (uint32_t*)(smem + (ch % 3) * STAGE_BYTES);
        uint32_t* Bbuf = (uint32_t*)(smem + (ch % 3) * STAGE_BYTES + HALF_STAGE);
#pragma unroll
        for (int ks = 0; ks < 4; ks++) {
            int kk = ks * 8 + kc;
            uint32_t a[2][4];
#pragma unroll
            for (int mt = 0; mt < 2; mt++) {
                int rb = a_base + mt * 16 * A_STRIDE;
                a[mt][0] = Abuf[rb + kk];
                a[mt][1] = Abuf[rb + 8 * A_STRIDE + kk];
                a[mt][2] = Abuf[rb + kk + 4];
                a[mt][3] = Abuf[rb + 8 * A_STRIDE + kk + 4];
            }
            uint32_t b[8][2];
#pragma unroll
            for (int nt = 0; nt < 8; nt++) {
                int nb = b_base + nt * 8 * A_STRIDE;
                b[nt][0] = Bbuf[nb + kk];
                b[nt][1] = Bbuf[nb + kk + 4];
            }
#pragma unroll
            for (int mt = 0; mt < 2; mt++)
#pragma unroll
                for (int nt = 0; nt < 8; nt++)
                    mma16(acc[mt][nt], a[mt], b[nt]);
        }

        if (ch < 3) {
            if (ch < 2) {
                prefetch(ch + 2);
                CP_COMMIT();
                CP_WAIT1();
            } else {
                CP_WAIT0();
            }
            __syncthreads();
        }
    }

    // ---- fused LSTM epilogue (half outputs) + per-row logit partials ----
    const float2* Wr2 = (const float2*)Wr;
    const float2* Wb2 = (const float2*)Wb;
#pragma unroll
    for (int mt = 0; mt < 2; mt++) {
        int r = row0 + wm * 32 + mt * 16 + (lane >> 2);
        float s0a = 0.f, s1a = 0.f, s2a = 0.f, s3a = 0.f;
        float s0b = 0.f, s1b = 0.f, s2b = 0.f, s3b = 0.f;
#pragma unroll
        for (int p = 0; p < 4; p++) {
            int u = (col0 >> 2) + wn * 16 + p * 4 + (lane & 3);
            float co0 = Cold[(size_t)r * PH + u];
            float co1 = Cold[(size_t)(r + 8) * PH + u];
            float iv = acc[mt][2 * p][0] + bI[p];
            float fv = acc[mt][2 * p][1] + bF[p];
            float gv = acc[mt][2 * p + 1][0] + bG[p];
            float ov = acc[mt][2 * p + 1][1] + bO[p];
            float cn0 = sigf(fv) * co0 + sigf(iv) * tanhf_f(gv);
            float hn0 = sigf(ov) * tanhf_f(cn0);
            float iv1 = acc[mt][2 * p][2] + bI[p];
            float fv1 = acc[mt][2 * p][3] + bF[p];
            float gv1 = acc[mt][2 * p + 1][2] + bG[p];
            float ov1 = acc[mt][2 * p + 1][3] + bO[p];
            float cn1 = sigf(fv1) * co1 + sigf(iv1) * tanhf_f(gv1);
            float hn1 = sigf(ov1) * tanhf_f(cn1);

            outC[(size_t)r * PG4 + u] = __float2half_rn(cn0);
            outH[(size_t)r * PG4 + u] = __float2half_rn(hn0);
            outC[(size_t)(r + 8) * PG4 + u] = __float2half_rn(cn1);
            outH[(size_t)(r + 8) * PG4 + u] = __float2half_rn(hn1);

            int pc = cbase + u, ph = pc + 128;
            float2 wrc = Wr2[pc], wrh = Wr2[ph];
            float2 wbc = Wb2[pc], wbh = Wb2[ph];
            s0a = fmaf(cn0, wrc.x, fmaf(hn0, wrh.x, s0a));
            s1a = fmaf(cn0, wrc.y, fmaf(hn0, wrh.y, s1a));
            s2a = fmaf(cn0, wbc.x, fmaf(hn0, wbh.x, s2a));
            s3a = fmaf(cn0, wbc.y, fmaf(hn0, wbh.y, s3a));
            s0b = fmaf(cn1, wrc.x, fmaf(hn1, wrh.x, s0b));
            s1b = fmaf(cn1, wrc.y, fmaf(hn1, wrh.y, s1b));
            s2b = fmaf(cn1, wbc.x, fmaf(hn1, wbh.x, s2b));
            s3b = fmaf(cn1, wbc.y, fmaf(hn1, wbh.y, s3b));
        }
#pragma unroll
        for (int o = 1; o <= 2; o <<= 1) {
            s0a += __shfl_xor_sync(0xffffffffu, s0a, o);
            s1a += __shfl_xor_sync(0xffffffffu, s1a, o);
            s2a += __shfl_xor_sync(0xffffffffu, s2a, o);
            s3a += __shfl_xor_sync(0xffffffffu, s3a, o);
            s0b += __shfl_xor_sync(0xffffffffu, s0b, o);
            s1b += __shfl_xor_sync(0xffffffffu, s1b, o);
            s2b += __shfl_xor_sync(0xffffffffu, s2b, o);
            s3b += __shfl_xor_sync(0xffffffffu, s3b, o);
        }
        if ((lane & 3) == 0) {
            red4(&g_logits[(size_t)r * 4], s0a, s1a, s2a, s3a);
            red4(&g_logits[(size_t)(r + 8) * 4], s0b, s1b, s2b, s3b);
        }
    }
}

// ---------------- mask exit/raise nodes: contrib <- old state (half) ---------
__global__ void ip_mask(const float* __restrict__ hc0, const float* __restrict__ hh0,
                        const float* __restrict__ hc1, const float* __restrict__ hh1,
                        const int* __restrict__ exi, const int* __restrict__ rai)
{
    int b = blockIdx.x;
    int node = blockIdx.y ? rai[b] : exi[b];
    int tid = threadIdx.x;  // 128
    size_t r = (size_t)b * PN + node;
    __half* dst = g_contrib + r * PG4;
    size_t rb = r * PH;
    dst[tid]       = __float2half_rn(hc0[rb + tid]);
    dst[128 + tid] = __float2half_rn(hh0[rb + tid]);
    dst[256 + tid] = __float2half_rn(hc1[rb + tid]);
    dst[384 + tid] = __float2half_rn(hh1[rb + tid]);
}

// ---------------- recompute logits for masked rows (half contrib) ------------
__global__ void ip_fixlog(const int* __restrict__ exi, const int* __restrict__ rai,
                          const float* __restrict__ Wr, const float* __restrict__ Wb)
{
    int b = blockIdx.x;
    int node = blockIdx.y ? rai[b] : exi[b];
    int lane = threadIdx.x;  // 32
    int row = (b << 11) + node;
    const __half2* crow = (const __half2*)(g_contrib + (size_t)row * PG4);

    float r0 = 0.f, r1 = 0.f, q0 = 0.f, q1 = 0.f;
#pragma unroll
    for (int t2 = 0; t2 < 4; t2++) {
        int cb = lane * 4 + t2 * 128;            // half index, multiple of 4
        float2 f0 = __half22float2(crow[cb >> 1]);
        float2 f1 = __half22float2(crow[(cb >> 1) + 1]);
        float vv[4] = {f0.x, f0.y, f1.x, f1.y};
#pragma unroll
        for (int q = 0; q < 4; q++) {
            float w = vv[q];
            int c2 = (cb + q) * 2;
            r0 = fmaf(w, Wr[c2 + 0], r0);
            r1 = fmaf(w, Wr[c2 + 1], r1);
            q0 = fmaf(w, Wb[c2 + 0], q0);
            q1 = fmaf(w, Wb[c2 + 1], q1);
        }
    }
#pragma unroll
    for (int o = 16; o > 0; o >>= 1) {
        r0 += __shfl_xor_sync(0xffffffffu, r0, o);
        r1 += __shfl_xor_sync(0xffffffffu, r1, o);
        q0 += __shfl_xor_sync(0xffffffffu, q0, o);
        q1 += __shfl_xor_sync(0xffffffffu, q1, o);
    }
    if (lane == 0)
        ((float4*)g_logits)[row] = make_float4(r0, r1, q0, q1);
}

// ---------------- edge weights from logits + CSR fill ----------------
__global__ __launch_bounds__(256) void ip_edges(
    const float* __restrict__ brs, const float* __restrict__ bbs,
    const float* __restrict__ ipin,
    const int* __restrict__ ti, const int* __restrict__ fi, const int* __restrict__ ri,
    const int* __restrict__ exi, const int* __restrict__ rai,
    const int* __restrict__ slim, const int* __restrict__ cstep, int cs_fallback)
{
    int row = blockIdx.x * 256 + threadIdx.x;
    int b = row >> 11, n = row & 2047;

    float4 L = ((const float4*)g_logits)[row];
    ((float4*)g_logits)[row] = make_float4(0.f, 0.f, 0.f, 0.f);  // self-clean

    int cs = cstep ? cstep[0] : cs_fallback;
    if (cs >= slim[b]) return;

    float lr = (L.x + brs[0]) - (L.y + brs[1]);
    float p_raise = sigf(lr);
    float p_no = 1.0f - p_raise;
    if (n == exi[b] || n == rai[b]) { p_raise = 0.0f; p_no = 1.0f; }
    float lb = (L.z + bbs[0]) - (L.w + bbs[1]);
    float pb0 = sigf(lb);
    float pb1 = 1.0f - pb0;

    float ipv = ipin[row];
    float wr_ = p_raise * ipv;
    float wt_ = p_no * pb0 * ipv;
    float wf_ = p_no * pb1 * ipv;

    int bb2 = b << 11;
    int tr = bb2 + ri[row], tt = bb2 + ti[row], tf = bb2 + fi[row];
    atomicAdd(&g_ipnew[tr], wr_);
    atomicAdd(&g_ipnew[tt], wt_);
    atomicAdd(&g_ipnew[tf], wf_);
    if (wr_ != 0.0f) {
        int s = atomicAdd(&g_cur[tr], 1);
        g_esrc[s] = row; g_ew[s] = wr_;
    }
    if (wt_ != 0.0f) {
        int s = atomicAdd(&g_cur[tt], 1);
        g_esrc[s] = row; g_ew[s] = wt_;
    }
    if (wf_ != 0.0f) {
        int s = atomicAdd(&g_cur[tf], 1);
        g_esrc[s] = row; g_ew[s] = wf_;
    }
}

// ---------------- gather + finalize (half contrib reads) ----------------
__global__ __launch_bounds__(128) void ip_gather(
    const float* __restrict__ hc0, const float* __restrict__ hh0,
    const float* __restrict__ hc1, const float* __restrict__ hh1,
    const float* __restrict__ ipold, const int* __restrict__ slim,
    const int* __restrict__ cstep, int cs_fallback, float* __restrict__ out)
{
    int row = blockIdx.x;
    int tid = threadIdx.x;  // 128
    int b = row >> 11;
    int cs = cstep ? cstep[0] : cs_fallback;
    bool nd = cs < slim[b];
    size_t ob = (size_t)row * 513;
    if (nd) {
        int s = g_off[row], e = g_cur[row];
        const __half2* cb = (const __half2*)g_contrib;   // 256 half2 per row
        float ax = 0.f, ay = 0.f, az = 0.f, aw = 0.f;
        for (int i = s; i < e; i++) {
            float w = g_ew[i];
            int src = g_esrc[i];
            size_t base = (size_t)src * 256 + 2 * tid;
            float2 f0 = __half22float2(cb[base]);
            float2 f1 = __half22float2(cb[base + 1]);
            ax = fmaf(w, f0.x, ax); ay = fmaf(w, f0.y, ay);
            az = fmaf(w, f1.x, az); aw = fmaf(w, f1.y, aw);
        }
        float ipn = g_ipnew[row];
        float inv = __fdividef(1.0f, ipn + 1e-7f);
        out[ob + 4 * tid + 0] = ax * inv;
        out[ob + 4 * tid + 1] = ay * inv;
        out[ob + 4 * tid + 2] = az * inv;
        out[ob + 4 * tid + 3] = aw * inv;
        if (tid == 0) out[ob + 512] = ipn;
    } else {
        size_t rb = (size_t)row * PH;
        out[ob + tid]       = hc0[rb + tid];
        out[ob + 128 + tid] = hh0[rb + tid];
        out[ob + 256 + tid] = hc1[rb + tid];
        out[ob + 384 + tid] = hh1[rb + tid];
        if (tid == 0) out[ob + 512] = ipold[row];
    }
}

// ---------------- host launcher ----------------
extern "C" void kernel_launch(void* const* d_in, const int* in_sizes, int n_in,
                              void* d_out, int out_size)
{
    const float* emb  = (const float*)d_in[0];
    const float* hc0  = (const float*)d_in[1];
    const float* hh0  = (const float*)d_in[2];
    const float* hc1  = (const float*)d_in[3];
    const float* hh1  = (const float*)d_in[4];
    const float* ip   = (const float*)d_in[5];
    const float* Wi0  = (const float*)d_in[6];
    const float* Wh0  = (const float*)d_in[7];
    const float* b0   = (const float*)d_in[8];
    const float* Wi1  = (const float*)d_in[9];
    const float* Wh1  = (const float*)d_in[10];
    const float* b1   = (const float*)d_in[11];
    const float* Wr   = (const float*)d_in[12];
    const float* br   = (const float*)d_in[13];
    const float* Wb   = (const float*)d_in[14];
    const float* bb   = (const float*)d_in[15];
    const int* ti     = (const int*)d_in[16];
    const int* fi     = (const int*)d_in[17];
    const int* ri     = (const int*)d_in[18];
    const int* exi    = (const int*)d_in[19];
    const int* rai    = (const int*)d_in[20];
    const int* slim   = (const int*)d_in[21];
    const int* cstep  = (n_in >= 23) ? (const int*)d_in[22] : nullptr;
    float* out = (float*)d_out;

    float *bP0, *bP1;
    __half *contrib, *A0, *H1h, *WT0h, *WT1h;
    cudaGetSymbolAddress((void**)&contrib, g_contrib);
    cudaGetSymbolAddress((void**)&A0,      g_A0);
    cudaGetSymbolAddress((void**)&H1h,     g_H1h);
    cudaGetSymbolAddress((void**)&WT0h,    g_WT0h);
    cudaGetSymbolAddress((void**)&WT1h,    g_WT1h);
    cudaGetSymbolAddress((void**)&bP0,     g_bP0);
    cudaGetSymbolAddress((void**)&bP1,     g_bP1);

    cudaFuncSetAttribute(ip_lstm_mma,
                         cudaFuncAttributeMaxDynamicSharedMemorySize, SMEM_TOTAL_GEMM);

    // kernels 0-2, then gemm0 at kernel index 3 (ncu capture slot)
    ip_cvt16<<<dim3(PM * PH / 4 / 256, 3), 256>>>(emb, hh0, hh1);     // 0
    ip_permW<<<512, 256>>>(Wi0, Wh0, b0, WT0h, bP0);                  // 1
    ip_permW<<<512, 256>>>(Wi1, Wh1, b1, WT1h, bP1);                  // 2

    dim3 ggrid(4, PM / 128);
    // Layer 0 (kernel 3): A chunks 0-3 all from g_A0 ([emb|hh0], stride 256)
    ip_lstm_mma<<<ggrid, 256, SMEM_TOTAL_GEMM>>>(
        A0, PK, A0 + 128, PK, hc0, WT0h, bP0, Wr, Wb, 0,
        contrib + 0, contrib + 128);
    // Layer 1 (kernel 4): A chunks 0-1 = h0n (contrib+128, stride 512),
    //                     chunks 2-3 = hh1 (g_H1h, stride 128)
    ip_lstm_mma<<<ggrid, 256, SMEM_TOTAL_GEMM>>>(
        contrib + 128, PG4, H1h, PH, hc1, WT1h, bP1, Wr, Wb, 256,
        contrib + 256, contrib + 384);

    ip_count<<<PM / 256, 256>>>(ti, fi, ri);

    ip_scan<<<PB, 512>>>();

    ip_mask<<<dim3(PB, 2), 128>>>(hc0, hh0, hc1, hh1, exi, rai);

    ip_fixlog<<<dim3(PB, 2), 32>>>(exi, rai, Wr, Wb);

    ip_edges<<<PM / 256, 256>>>(br, bb, ip, ti, fi, ri, exi, rai, slim, cstep, 5);

    ip_gather<<<PM, 128>>>(hc0, hh0, hc1, hh1, ip, slim, cstep, 5, out);
}

// round 15
// speedup vs baseline: 1.3915x; 1.0096x over previous
#include <cuda_runtime.h>
#include <cuda_fp16.h>
#include <math.h>
#include <stdint.h>

// Problem constants
#define PB 32
#define PN 2048
#define PH 128
#define PG4 512
#define PM (PB * PN)   // 65536 rows
#define PK 256         // combined K = [X | H]

// ---------------- device scratch (no allocations allowed) ----------------
__device__ __half g_contrib[(size_t)PM * PG4];  // [c0 | h0 | c1 | h1] per row (fp16)
__device__ __half g_A0[(size_t)PM * PK];        // layer0 A: [emb | hh0] half
__device__ __half g_H1h[(size_t)PM * PH];       // hh1 half (layer1 A high-K source)
__device__ __half g_WT0h[PG4 * PK];             // layer0 weights [n][k] half
__device__ __half g_WT1h[PG4 * PK];             // layer1 weights half
__device__ float  g_bP0[PG4];
__device__ float  g_bP1[PG4];
__device__ float  g_logits[(size_t)PM * 4];     // per-row [r0, r1, b0, b1]
__device__ float  g_ipnew[PM];
__device__ int    g_off[PM];
__device__ int    g_cur[PM];
__device__ int    g_esrc[3 * PM];
__device__ float  g_ew[3 * PM];

// ---------------- helpers ----------------
__device__ __forceinline__ uint32_t smem_u32(const void* p) {
    uint32_t a;
    asm("{ .reg .u64 t; cvta.to.shared.u64 t, %1; cvt.u32.u64 %0, t; }" : "=r"(a) : "l"(p));
    return a;
}
__device__ __forceinline__ void mma16(float* d, const uint32_t* a, const uint32_t* b) {
    asm volatile(
        "mma.sync.aligned.m16n8k16.row.col.f32.f16.f16.f32 "
        "{%0,%1,%2,%3}, {%4,%5,%6,%7}, {%8,%9}, {%0,%1,%2,%3};"
        : "+f"(d[0]), "+f"(d[1]), "+f"(d[2]), "+f"(d[3])
        : "r"(a[0]), "r"(a[1]), "r"(a[2]), "r"(a[3]), "r"(b[0]), "r"(b[1]));
}
__device__ __forceinline__ void red4(float* p, float a, float b, float c, float d) {
    asm volatile("red.global.add.v4.f32 [%0], {%1,%2,%3,%4};"
                 :: "l"(p), "f"(a), "f"(b), "f"(c), "f"(d) : "memory");
}
#define CP_ASYNC16(s, g) asm volatile("cp.async.cg.shared.global [%0], [%1], 16;" :: "r"(s), "l"(g))
#define CP_COMMIT() asm volatile("cp.async.commit_group;" ::: "memory")
#define CP_WAIT0() asm volatile("cp.async.wait_group 0;" ::: "memory")
#define CP_WAIT1() asm volatile("cp.async.wait_group 1;" ::: "memory")

__device__ __forceinline__ float sigf(float x) {
    return __fdividef(1.0f, 1.0f + __expf(-x));
}
__device__ __forceinline__ float tanhf_f(float x) {
    float xc = fminf(fmaxf(x, -15.0f), 15.0f);
    float e = __expf(2.0f * xc);
    return __fdividef(e - 1.0f, e + 1.0f);
}

// ---------------- prelude: pack A operands as half ----------------
__global__ void ip_cvt16(const float* __restrict__ emb, const float* __restrict__ hh0,
                         const float* __restrict__ hh1)
{
    int i = blockIdx.x * 256 + threadIdx.x;     // [0, PM*PH/4)
    int s = blockIdx.y;
    const float4* src = (const float4*)(s == 0 ? emb : (s == 1 ? hh0 : hh1));
    float4 v = src[i];
    int r = i >> 5, c4 = i & 31;
    __half2 h0 = __floats2half2_rn(v.x, v.y);
    __half2 h1 = __floats2half2_rn(v.z, v.w);
    if (s == 2) {
        __half2* dst = (__half2*)g_H1h;
        int off = r * 64 + c4 * 2;
        dst[off] = h0; dst[off + 1] = h1;
    } else {
        __half2* dst = (__half2*)g_A0;
        int off = r * 128 + (s == 0 ? 0 : 64) + c4 * 2;
        dst[off] = h0; dst[off + 1] = h1;
    }
}

// ---------------- weight prep (half) ----------------
__device__ __forceinline__ int perm_oc(int n) {
    int blk = n >> 4, w = n & 15;
    int ghi = w >> 3, pos = (w & 7) >> 1, glo = w & 1;
    int u = blk * 4 + pos;
    int g = ghi * 2 + glo;
    return g * 128 + u;
}
__global__ void ip_permW(const float* __restrict__ Wi, const float* __restrict__ Wh,
                         const float* __restrict__ bsrc,
                         __half* __restrict__ WT, float* __restrict__ bdst)
{
    int t = blockIdx.x * 256 + threadIdx.x;
    int n = t >> 8;
    int k = t & 255;
    int oc = perm_oc(n);
    float w = (k < 128) ? Wi[k * PG4 + oc] : Wh[(k - 128) * PG4 + oc];
    WT[t] = __float2half_rn(w);
    if (k == 0) bdst[n] = bsrc[oc];
}

// ---------------- fused CSR: smem count + scan; zeroes ipnew ----------------
__global__ __launch_bounds__(512) void ip_csr(const int* __restrict__ ti,
                                              const int* __restrict__ fi,
                                              const int* __restrict__ ri)
{
    __shared__ int scnt[2048];
    __shared__ int part[512];
    int b = blockIdx.x;          // 32 batches
    int t = threadIdx.x;         // 512
    int base = b << 11;

#pragma unroll
    for (int j = 0; j < 4; j++) scnt[t + j * 512] = 0;
    __syncthreads();
#pragma unroll
    for (int j = 0; j < 4; j++) {
        int row = base + t + j * 512;
        atomicAdd(&scnt[ri[row]], 1);
        atomicAdd(&scnt[ti[row]], 1);
        atomicAdd(&scnt[fi[row]], 1);
    }
    __syncthreads();

    int c0 = scnt[4 * t + 0];
    int c1 = scnt[4 * t + 1];
    int c2 = scnt[4 * t + 2];
    int c3 = scnt[4 * t + 3];
    int l0 = c0, l1 = l0 + c1, l2 = l1 + c2, l3 = l2 + c3;
    part[t] = l3;
    __syncthreads();
    for (int o = 1; o < 512; o <<= 1) {
        int v = (t >= o) ? part[t - o] : 0;
        __syncthreads();
        part[t] += v;
        __syncthreads();
    }
    int ex = (t == 0) ? 0 : part[t - 1];
    int gb = b * 6144 + ex;
    g_off[base + 4 * t + 0] = gb;
    g_off[base + 4 * t + 1] = gb + l0;
    g_off[base + 4 * t + 2] = gb + l1;
    g_off[base + 4 * t + 3] = gb + l2;
    g_cur[base + 4 * t + 0] = gb;
    g_cur[base + 4 * t + 1] = gb + l0;
    g_cur[base + 4 * t + 2] = gb + l1;
    g_cur[base + 4 * t + 3] = gb + l2;
    g_ipnew[base + 4 * t + 0] = 0.0f;
    g_ipnew[base + 4 * t + 1] = 0.0f;
    g_ipnew[base + 4 * t + 2] = 0.0f;
    g_ipnew[base + 4 * t + 3] = 0.0f;
}

// ---------------- fp16 mma.sync GEMM + fused LSTM + logit epilogue ----------
// CTA 128x128, 8 warps (4M x 2N). K=256 in 4 chunks of 64 halves (128B rows,
// padded to 144B). 3-stage all-cp.async pipeline. A split across two sources.
#define A_STRIDE 36                               // words per row (144 B)
#define HALF_STAGE (128 * A_STRIDE * 4)           // 18432
#define STAGE_BYTES (2 * HALF_STAGE)              // 36864
#define SMEM_TOTAL_GEMM (3 * STAGE_BYTES)         // 110592

__global__ __launch_bounds__(256, 2) void ip_lstm_mma(
    const __half* __restrict__ A0p, int as0,
    const __half* __restrict__ A1p, int as1,
    const float* __restrict__ Cold,
    const __half* __restrict__ WT, const float* __restrict__ bP,
    const float* __restrict__ Wr, const float* __restrict__ Wb, int cbase,
    __half* __restrict__ outC, __half* __restrict__ outH)
{
    extern __shared__ char smem[];

    int tid = threadIdx.x;
    int wid = tid >> 5, lane = tid & 31;
    int wm = wid & 3, wn = wid >> 2;
    int row0 = blockIdx.y * 128;
    int col0 = blockIdx.x * 128;

    float acc[2][8][4];
#pragma unroll
    for (int mt = 0; mt < 2; mt++)
#pragma unroll
        for (int nt = 0; nt < 8; nt++)
#pragma unroll
            for (int q = 0; q < 4; q++) acc[mt][nt][q] = 0.0f;

    float bI[4], bF[4], bG[4], bO[4];
#pragma unroll
    for (int p = 0; p < 4; p++) {
        int c0 = col0 + wn * 64 + p * 16 + (lane & 3) * 2;
        bI[p] = bP[c0];     bF[p] = bP[c0 + 1];
        bG[p] = bP[c0 + 8]; bO[p] = bP[c0 + 9];
    }

    auto prefetch = [&](int c) {
        const __half* Asrc;
        int astr, kh;
        if (c < 2) { Asrc = A0p; astr = as0; kh = c * 64; }
        else       { Asrc = A1p; astr = as1; kh = (c - 2) * 64; }
        int kb = c * 64;
        char* As = smem + (c % 3) * STAGE_BYTES;
        char* Bs = As + HALF_STAGE;
#pragma unroll
        for (int j = 0; j < 4; j++) {
            int fid = j * 256 + tid;              // [0,1024)
            int r = fid >> 3, q = fid & 7;
            CP_ASYNC16(smem_u32(As + r * 144 + q * 16),
                       Asrc + (size_t)(row0 + r) * astr + kh + q * 8);
            CP_ASYNC16(smem_u32(Bs + r * 144 + q * 16),
                       WT + (size_t)(col0 + r) * PK + kb + q * 8);
        }
    };

    prefetch(0); CP_COMMIT();
    prefetch(1); CP_COMMIT();
    CP_WAIT1();
    __syncthreads();

    int a_base = (wm * 32 + (lane >> 2)) * A_STRIDE;
    int b_base = (wn * 64 + (lane >> 2)) * A_STRIDE;
    int kc = lane & 3;

#pragma unroll 1
    for (int ch = 0; ch < 4; ch++) {
        uint32_t* Abuf = (uint32_t*)(smem + (ch % 3) * STAGE_BYTES);
        uint32_t* Bbuf = (uint32_t*)(smem + (ch % 3) * STAGE_BYTES + HALF_STAGE);
#pragma unroll
        for (int ks = 0; ks < 4; ks++) {
            int kk = ks * 8 + kc;
            uint32_t a[2][4];
#pragma unroll
            for (int mt = 0; mt < 2; mt++) {
                int rb = a_base + mt * 16 * A_STRIDE;
                a[mt][0] = Abuf[rb + kk];
                a[mt][1] = Abuf[rb + 8 * A_STRIDE + kk];
                a[mt][2] = Abuf[rb + kk + 4];
                a[mt][3] = Abuf[rb + 8 * A_STRIDE + kk + 4];
            }
            uint32_t b[8][2];
#pragma unroll
            for (int nt = 0; nt < 8; nt++) {
                int nb = b_base + nt * 8 * A_STRIDE;
                b[nt][0] = Bbuf[nb + kk];
                b[nt][1] = Bbuf[nb + kk + 4];
            }
#pragma unroll
            for (int mt = 0; mt < 2; mt++)
#pragma unroll
                for (int nt = 0; nt < 8; nt++)
                    mma16(acc[mt][nt], a[mt], b[nt]);
        }

        if (ch < 3) {
            if (ch < 2) {
                prefetch(ch + 2);
                CP_COMMIT();
                CP_WAIT1();
            } else {
                CP_WAIT0();
            }
            __syncthreads();
        }
    }

    // ---- fused LSTM epilogue (half outputs) + per-row logit partials ----
    const float2* Wr2 = (const float2*)Wr;
    const float2* Wb2 = (const float2*)Wb;
#pragma unroll
    for (int mt = 0; mt < 2; mt++) {
        int r = row0 + wm * 32 + mt * 16 + (lane >> 2);
        float s0a = 0.f, s1a = 0.f, s2a = 0.f, s3a = 0.f;
        float s0b = 0.f, s1b = 0.f, s2b = 0.f, s3b = 0.f;
#pragma unroll
        for (int p = 0; p < 4; p++) {
            int u = (col0 >> 2) + wn * 16 + p * 4 + (lane & 3);
            float co0 = Cold[(size_t)r * PH + u];
            float co1 = Cold[(size_t)(r + 8) * PH + u];
            float iv = acc[mt][2 * p][0] + bI[p];
            float fv = acc[mt][2 * p][1] + bF[p];
            float gv = acc[mt][2 * p + 1][0] + bG[p];
            float ov = acc[mt][2 * p + 1][1] + bO[p];
            float cn0 = sigf(fv) * co0 + sigf(iv) * tanhf_f(gv);
            float hn0 = sigf(ov) * tanhf_f(cn0);
            float iv1 = acc[mt][2 * p][2] + bI[p];
            float fv1 = acc[mt][2 * p][3] + bF[p];
            float gv1 = acc[mt][2 * p + 1][2] + bG[p];
            float ov1 = acc[mt][2 * p + 1][3] + bO[p];
            float cn1 = sigf(fv1) * co1 + sigf(iv1) * tanhf_f(gv1);
            float hn1 = sigf(ov1) * tanhf_f(cn1);

            outC[(size_t)r * PG4 + u] = __float2half_rn(cn0);
            outH[(size_t)r * PG4 + u] = __float2half_rn(hn0);
            outC[(size_t)(r + 8) * PG4 + u] = __float2half_rn(cn1);
            outH[(size_t)(r + 8) * PG4 + u] = __float2half_rn(hn1);

            int pc = cbase + u, ph = pc + 128;
            float2 wrc = Wr2[pc], wrh = Wr2[ph];
            float2 wbc = Wb2[pc], wbh = Wb2[ph];
            s0a = fmaf(cn0, wrc.x, fmaf(hn0, wrh.x, s0a));
            s1a = fmaf(cn0, wrc.y, fmaf(hn0, wrh.y, s1a));
            s2a = fmaf(cn0, wbc.x, fmaf(hn0, wbh.x, s2a));
            s3a = fmaf(cn0, wbc.y, fmaf(hn0, wbh.y, s3a));
            s0b = fmaf(cn1, wrc.x, fmaf(hn1, wrh.x, s0b));
            s1b = fmaf(cn1, wrc.y, fmaf(hn1, wrh.y, s1b));
            s2b = fmaf(cn1, wbc.x, fmaf(hn1, wbh.x, s2b));
            s3b = fmaf(cn1, wbc.y, fmaf(hn1, wbh.y, s3b));
        }
#pragma unroll
        for (int o = 1; o <= 2; o <<= 1) {
            s0a += __shfl_xor_sync(0xffffffffu, s0a, o);
            s1a += __shfl_xor_sync(0xffffffffu, s1a, o);
            s2a += __shfl_xor_sync(0xffffffffu, s2a, o);
            s3a += __shfl_xor_sync(0xffffffffu, s3a, o);
            s0b += __shfl_xor_sync(0xffffffffu, s0b, o);
            s1b += __shfl_xor_sync(0xffffffffu, s1b, o);
            s2b += __shfl_xor_sync(0xffffffffu, s2b, o);
            s3b += __shfl_xor_sync(0xffffffffu, s3b, o);
        }
        if ((lane & 3) == 0) {
            red4(&g_logits[(size_t)r * 4], s0a, s1a, s2a, s3a);
            red4(&g_logits[(size_t)(r + 8) * 4], s0b, s1b, s2b, s3b);
        }
    }
}

// ---------------- fused mask + logit recompute for exit/raise rows ----------
__global__ void ip_maskfix(const float* __restrict__ hc0, const float* __restrict__ hh0,
                           const float* __restrict__ hc1, const float* __restrict__ hh1,
                           const int* __restrict__ exi, const int* __restrict__ rai,
                           const float* __restrict__ Wr, const float* __restrict__ Wb)
{
    __shared__ float red[4][4];   // [warp][logit]
    int b = blockIdx.x;
    int node = blockIdx.y ? rai[b] : exi[b];
    int tid = threadIdx.x;        // 128
    int wrp = tid >> 5, lane = tid & 31;
    int row = (b << 11) + node;
    size_t r = (size_t)b * PN + node;
    __half* dst = g_contrib + r * PG4;
    size_t rb = r * PH;

    // mask write (half-rounded), keep rounded values for logits
    float v[4];
    v[0] = hc0[rb + tid]; v[1] = hh0[rb + tid];
    v[2] = hc1[rb + tid]; v[3] = hh1[rb + tid];
    float s0 = 0.f, s1 = 0.f, s2 = 0.f, s3 = 0.f;
#pragma unroll
    for (int q = 0; q < 4; q++) {
        __half h = __float2half_rn(v[q]);
        dst[q * 128 + tid] = h;
        float w = __half2float(h);
        int c2 = (q * 128 + tid) * 2;
        s0 = fmaf(w, Wr[c2 + 0], s0);
        s1 = fmaf(w, Wr[c2 + 1], s1);
        s2 = fmaf(w, Wb[c2 + 0], s2);
        s3 = fmaf(w, Wb[c2 + 1], s3);
    }
#pragma unroll
    for (int o = 16; o > 0; o >>= 1) {
        s0 += __shfl_xor_sync(0xffffffffu, s0, o);
        s1 += __shfl_xor_sync(0xffffffffu, s1, o);
        s2 += __shfl_xor_sync(0xffffffffu, s2, o);
        s3 += __shfl_xor_sync(0xffffffffu, s3, o);
    }
    if (lane == 0) {
        red[wrp][0] = s0; red[wrp][1] = s1; red[wrp][2] = s2; red[wrp][3] = s3;
    }
    __syncthreads();
    if (tid == 0) {
        float r0 = red[0][0] + red[1][0] + red[2][0] + red[3][0];
        float r1 = red[0][1] + red[1][1] + red[2][1] + red[3][1];
        float q0 = red[0][2] + red[1][2] + red[2][2] + red[3][2];
        float q1 = red[0][3] + red[1][3] + red[2][3] + red[3][3];
        ((float4*)g_logits)[row] = make_float4(r0, r1, q0, q1);
    }
}

// ---------------- edge weights from logits + CSR fill ----------------
__global__ __launch_bounds__(256) void ip_edges(
    const float* __restrict__ brs, const float* __restrict__ bbs,
    const float* __restrict__ ipin,
    const int* __restrict__ ti, const int* __restrict__ fi, const int* __restrict__ ri,
    const int* __restrict__ exi, const int* __restrict__ rai,
    const int* __restrict__ slim, const int* __restrict__ cstep, int cs_fallback)
{
    int row = blockIdx.x * 256 + threadIdx.x;
    int b = row >> 11, n = row & 2047;

    float4 L = ((const float4*)g_logits)[row];
    ((float4*)g_logits)[row] = make_float4(0.f, 0.f, 0.f, 0.f);  // self-clean

    int cs = cstep ? cstep[0] : cs_fallback;
    if (cs >= slim[b]) return;

    float lr = (L.x + brs[0]) - (L.y + brs[1]);
    float p_raise = sigf(lr);
    float p_no = 1.0f - p_raise;
    if (n == exi[b] || n == rai[b]) { p_raise = 0.0f; p_no = 1.0f; }
    float lb = (L.z + bbs[0]) - (L.w + bbs[1]);
    float pb0 = sigf(lb);
    float pb1 = 1.0f - pb0;

    float ipv = ipin[row];
    float wr_ = p_raise * ipv;
    float wt_ = p_no * pb0 * ipv;
    float wf_ = p_no * pb1 * ipv;

    int bb2 = b << 11;
    int tr = bb2 + ri[row], tt = bb2 + ti[row], tf = bb2 + fi[row];
    atomicAdd(&g_ipnew[tr], wr_);
    atomicAdd(&g_ipnew[tt], wt_);
    atomicAdd(&g_ipnew[tf], wf_);
    if (wr_ != 0.0f) {
        int s = atomicAdd(&g_cur[tr], 1);
        g_esrc[s] = row; g_ew[s] = wr_;
    }
    if (wt_ != 0.0f) {
        int s = atomicAdd(&g_cur[tt], 1);
        g_esrc[s] = row; g_ew[s] = wt_;
    }
    if (wf_ != 0.0f) {
        int s = atomicAdd(&g_cur[tf], 1);
        g_esrc[s] = row; g_ew[s] = wf_;
    }
}

// ---------------- gather + finalize (2 rows per block) ----------------
__global__ __launch_bounds__(256) void ip_gather(
    const float* __restrict__ hc0, const float* __restrict__ hh0,
    const float* __restrict__ hc1, const float* __restrict__ hh1,
    const float* __restrict__ ipold, const int* __restrict__ slim,
    const int* __restrict__ cstep, int cs_fallback, float* __restrict__ out)
{
    int row = blockIdx.x * 2 + (threadIdx.x >> 7);
    int tid = threadIdx.x & 127;
    int b = row >> 11;
    int cs = cstep ? cstep[0] : cs_fallback;
    bool nd = cs < slim[b];
    size_t ob = (size_t)row * 513;
    if (nd) {
        int s = g_off[row], e = g_cur[row];
        const __half2* cb = (const __half2*)g_contrib;   // 256 half2 per row
        float ax = 0.f, ay = 0.f, az = 0.f, aw = 0.f;
        for (int i = s; i < e; i++) {
            float w = g_ew[i];
            int src = g_esrc[i];
            size_t base = (size_t)src * 256 + 2 * tid;
            float2 f0 = __half22float2(cb[base]);
            float2 f1 = __half22float2(cb[base + 1]);
            ax = fmaf(w, f0.x, ax); ay = fmaf(w, f0.y, ay);
            az = fmaf(w, f1.x, az); aw = fmaf(w, f1.y, aw);
        }
        float ipn = g_ipnew[row];
        float inv = __fdividef(1.0f, ipn + 1e-7f);
        out[ob + 4 * tid + 0] = ax * inv;
        out[ob + 4 * tid + 1] = ay * inv;
        out[ob + 4 * tid + 2] = az * inv;
        out[ob + 4 * tid + 3] = aw * inv;
        if (tid == 0) out[ob + 512] = ipn;
    } else {
        size_t rb = (size_t)row * PH;
        out[ob + tid]       = hc0[rb + tid];
        out[ob + 128 + tid] = hh0[rb + tid];
        out[ob + 256 + tid] = hc1[rb + tid];
        out[ob + 384 + tid] = hh1[rb + tid];
        if (tid == 0) out[ob + 512] = ipold[row];
    }
}

// ---------------- host launcher ----------------
extern "C" void kernel_launch(void* const* d_in, const int* in_sizes, int n_in,
                              void* d_out, int out_size)
{
    const float* emb  = (const float*)d_in[0];
    const float* hc0  = (const float*)d_in[1];
    const float* hh0  = (const float*)d_in[2];
    const float* hc1  = (const float*)d_in[3];
    const float* hh1  = (const float*)d_in[4];
    const float* ip   = (const float*)d_in[5];
    const float* Wi0  = (const float*)d_in[6];
    const float* Wh0  = (const float*)d_in[7];
    const float* b0   = (const float*)d_in[8];
    const float* Wi1  = (const float*)d_in[9];
    const float* Wh1  = (const float*)d_in[10];
    const float* b1   = (const float*)d_in[11];
    const float* Wr   = (const float*)d_in[12];
    const float* br   = (const float*)d_in[13];
    const float* Wb   = (const float*)d_in[14];
    const float* bb   = (const float*)d_in[15];
    const int* ti     = (const int*)d_in[16];
    const int* fi     = (const int*)d_in[17];
    const int* ri     = (const int*)d_in[18];
    const int* exi    = (const int*)d_in[19];
    const int* rai    = (const int*)d_in[20];
    const int* slim   = (const int*)d_in[21];
    const int* cstep  = (n_in >= 23) ? (const int*)d_in[22] : nullptr;
    float* out = (float*)d_out;

    float *bP0, *bP1;
    __half *contrib, *A0, *H1h, *WT0h, *WT1h;
    cudaGetSymbolAddress((void**)&contrib, g_contrib);
    cudaGetSymbolAddress((void**)&A0,      g_A0);
    cudaGetSymbolAddress((void**)&H1h,     g_H1h);
    cudaGetSymbolAddress((void**)&WT0h,    g_WT0h);
    cudaGetSymbolAddress((void**)&WT1h,    g_WT1h);
    cudaGetSymbolAddress((void**)&bP0,     g_bP0);
    cudaGetSymbolAddress((void**)&bP1,     g_bP1);

    cudaFuncSetAttribute(ip_lstm_mma,
                         cudaFuncAttributeMaxDynamicSharedMemorySize, SMEM_TOTAL_GEMM);

    // kernels 0-2, then gemm0 at kernel index 3 (ncu capture slot)
    ip_cvt16<<<dim3(PM * PH / 4 / 256, 3), 256>>>(emb, hh0, hh1);     // 0
    ip_permW<<<512, 256>>>(Wi0, Wh0, b0, WT0h, bP0);                  // 1
    ip_permW<<<512, 256>>>(Wi1, Wh1, b1, WT1h, bP1);                  // 2

    dim3 ggrid(4, PM / 128);
    // Layer 0 (kernel 3): A chunks 0-3 all from g_A0 ([emb|hh0], stride 256)
    ip_lstm_mma<<<ggrid, 256, SMEM_TOTAL_GEMM>>>(
        A0, PK, A0 + 128, PK, hc0, WT0h, bP0, Wr, Wb, 0,
        contrib + 0, contrib + 128);
    // Layer 1 (kernel 4): A chunks 0-1 = h0n (contrib+128, stride 512),
    //                     chunks 2-3 = hh1 (g_H1h, stride 128)
    ip_lstm_mma<<<ggrid, 256, SMEM_TOTAL_GEMM>>>(
        contrib + 128, PG4, H1h, PH, hc1, WT1h, bP1, Wr, Wb, 256,
        contrib + 256, contrib + 384);

    ip_csr<<<PB, 512>>>(ti, fi, ri);

    ip_maskfix<<<dim3(PB, 2), 128>>>(hc0, hh0, hc1, hh1, exi, rai, Wr, Wb);

    ip_edges<<<PM / 256, 256>>>(br, bb, ip, ti, fi, ri, exi, rai, slim, cstep, 5);

    ip_gather<<<PM / 2, 256>>>(hc0, hh0, hc1, hh1, ip, slim, cstep, 5, out);
}